// round 2
// baseline (speedup 1.0000x reference)
#include <cuda_runtime.h>

#define NNODES 50000
#define FIN    512
#define H1N    8
#define C1N    16
#define F1     128      // H1*C1
#define F2     40
#define EMAX   800000
#define ETOTMAX (EMAX + NNODES)

// ---------------- static scratch (no allocations allowed) ----------------
__device__ float g_h1 [NNODES * F1];   // layer1 GEMM output
__device__ float g_h1a[NNODES * F1];   // layer1 activated output
__device__ float g_as1[NNODES * H1N];
__device__ float g_ad1[NNODES * H1N];
__device__ float g_h2 [NNODES * F2];   // layer2 GEMM output
__device__ float g_as2[NNODES];
__device__ float g_ad2[NNODES];
__device__ int   g_counts[NNODES];
__device__ int   g_rowptr[NNODES + 1];
__device__ int   g_cursor[NNODES];
__device__ int   g_csr[ETOTMAX];       // src node per CSR slot (sorted by dst)
__device__ int   g_bsum[64];

// ---------------- CSR build ----------------
__global__ void k_zero_counts() {
    int i = blockIdx.x * blockDim.x + threadIdx.x;
    if (i < NNODES) g_counts[i] = 0;
}

__global__ void k_count(const int* __restrict__ ei, int E, int Etot) {
    int i = blockIdx.x * blockDim.x + threadIdx.x;
    if (i >= Etot) return;
    int d = (i < E) ? ei[E + i] : (i - E);
    if (d < 0 || d >= NNODES) return;   // defensive: dtype surprise -> wrong, not crash
    atomicAdd(&g_counts[d], 1);
}

__global__ void k_scan1() {
    __shared__ int tmp[1024];
    int t = threadIdx.x;
    int gid = blockIdx.x * 1024 + t;
    int v = (gid < NNODES) ? g_counts[gid] : 0;
    tmp[t] = v;
    __syncthreads();
    for (int off = 1; off < 1024; off <<= 1) {
        int x = (t >= off) ? tmp[t - off] : 0;
        __syncthreads();
        tmp[t] += x;
        __syncthreads();
    }
    if (gid < NNODES) g_rowptr[gid] = tmp[t] - v;   // exclusive within block
    if (t == 1023) g_bsum[blockIdx.x] = tmp[1023];
}

__global__ void k_scan2(int nb) {
    if (threadIdx.x == 0) {
        int acc = 0;
        for (int i = 0; i < nb; i++) { int x = g_bsum[i]; g_bsum[i] = acc; acc += x; }
    }
}

__global__ void k_scan3(int Etot) {
    int gid = blockIdx.x * blockDim.x + threadIdx.x;
    if (gid < NNODES) {
        int v = g_rowptr[gid] + g_bsum[gid >> 10];
        g_rowptr[gid] = v;
        g_cursor[gid] = v;
    }
    if (gid == 0) g_rowptr[NNODES] = Etot;
}

__global__ void k_fill(const int* __restrict__ ei, int E, int Etot) {
    int i = blockIdx.x * blockDim.x + threadIdx.x;
    if (i >= Etot) return;
    int s, d;
    if (i < E) { s = ei[i]; d = ei[E + i]; }
    else       { s = d = i - E; }
    if (d < 0 || d >= NNODES || s < 0 || s >= NNODES) return;
    int pos = atomicAdd(&g_cursor[d], 1);
    if (pos < ETOTMAX) g_csr[pos] = s;
}

// ---------------- GEMM1: h1 = x @ W1   (50000x512 @ 512x128) ----------------
// BM=64, BN=128, BK=16, 256 threads, each computes 8x4 outputs.
__global__ __launch_bounds__(256) void k_gemm1(const float* __restrict__ A,
                                               const float* __restrict__ B) {
    __shared__ float As[16][64];
    __shared__ float Bs[16][128];
    int bm  = blockIdx.x * 64;
    int tid = threadIdx.x;
    int tx  = tid & 31;      // col group: cols tx*4 .. tx*4+3
    int ty  = tid >> 5;      // row group: rows ty*8 .. ty*8+7

    float acc[8][4];
#pragma unroll
    for (int i = 0; i < 8; i++)
#pragma unroll
        for (int j = 0; j < 4; j++) acc[i][j] = 0.f;

    int arow = tid >> 2;          // 0..63
    int akq  = (tid & 3) * 4;     // 0,4,8,12

    for (int k0 = 0; k0 < FIN; k0 += 16) {
        // A tile: 64 rows x 16 k
        {
            int gr = bm + arow;
            float4 a = (gr < NNODES) ? *(const float4*)&A[(long)gr * FIN + k0 + akq]
                                     : make_float4(0.f, 0.f, 0.f, 0.f);
            As[akq + 0][arow] = a.x;
            As[akq + 1][arow] = a.y;
            As[akq + 2][arow] = a.z;
            As[akq + 3][arow] = a.w;
        }
        // B tile: 16 k x 128 cols = 512 float4, 2 per thread
#pragma unroll
        for (int l = 0; l < 2; l++) {
            int idx = tid + l * 256;
            int bk  = idx >> 5;
            int bc  = (idx & 31) * 4;
            *(float4*)&Bs[bk][bc] = *(const float4*)&B[(long)(k0 + bk) * F1 + bc];
        }
        __syncthreads();
#pragma unroll
        for (int k = 0; k < 16; k++) {
            float bv[4], av[8];
            *(float4*)bv      = *(float4*)&Bs[k][tx * 4];
            *(float4*)&av[0]  = *(float4*)&As[k][ty * 8];
            *(float4*)&av[4]  = *(float4*)&As[k][ty * 8 + 4];
#pragma unroll
            for (int i = 0; i < 8; i++)
#pragma unroll
                for (int j = 0; j < 4; j++) acc[i][j] += av[i] * bv[j];
        }
        __syncthreads();
    }
#pragma unroll
    for (int i = 0; i < 8; i++) {
        int gr = bm + ty * 8 + i;
        if (gr < NNODES)
            *(float4*)&g_h1[(long)gr * F1 + tx * 4] = *(float4*)&acc[i][0];
    }
}

// ---------------- attention coefficients, layer 1 ----------------
__global__ void k_coeff1(const float* __restrict__ att_s, const float* __restrict__ att_d) {
    int i = blockIdx.x * blockDim.x + threadIdx.x;   // (n,h)
    if (i >= NNODES * H1N) return;
    int n = i >> 3, h = i & 7;
    const float* hp = &g_h1[(long)n * F1 + h * C1N];
    float s = 0.f, d = 0.f;
#pragma unroll
    for (int c = 0; c < C1N; c++) {
        float v = hp[c];
        s += v * att_s[h * C1N + c];
        d += v * att_d[h * C1N + c];
    }
    g_as1[i] = s;
    g_ad1[i] = d;
}

// ---------------- layer-1 aggregation: warp per node, online softmax ----------------
__global__ void k_agg1(const float* __restrict__ b1) {
    int gtid = blockIdx.x * blockDim.x + threadIdx.x;
    int n    = gtid >> 5;
    int lane = threadIdx.x & 31;
    if (n >= NNODES) return;
    int h = lane >> 2;               // head for this lane's 4 channels
    int beg = g_rowptr[n], end = g_rowptr[n + 1];
    float adst = g_ad1[n * H1N + h];
    float m = -1e30f, s = 0.f;
    float ax = 0.f, ay = 0.f, az = 0.f, aw = 0.f;
    for (int j = beg; j < end; j++) {
        int src = g_csr[j];
        float e = g_as1[src * H1N + h] + adst;
        e = (e > 0.f) ? e : 0.2f * e;
        float mnew  = fmaxf(m, e);
        float scale = __expf(m - mnew);
        float w     = __expf(e - mnew);
        float4 v = *(const float4*)&g_h1[(long)src * F1 + lane * 4];
        s  = s  * scale + w;
        ax = ax * scale + w * v.x;
        ay = ay * scale + w * v.y;
        az = az * scale + w * v.z;
        aw = aw * scale + w * v.w;
        m = mnew;
    }
    float inv = 1.f / (s + 1e-16f);
    float o[4];
    o[0] = ax * inv + b1[lane * 4 + 0];
    o[1] = ay * inv + b1[lane * 4 + 1];
    o[2] = az * inv + b1[lane * 4 + 2];
    o[3] = aw * inv + b1[lane * 4 + 3];
#pragma unroll
    for (int i = 0; i < 4; i++)
        o[i] = (o[i] > 0.f) ? o[i] : (__expf(o[i]) - 1.f);   // ELU
    *(float4*)&g_h1a[(long)n * F1 + lane * 4] = *(float4*)o;
}

// ---------------- GEMM2: h2 = h1a @ W2   (50000x128 @ 128x40) ----------------
// BM=32 so static shared = 16KB + 20KB = 36KB (<48KB limit).
__global__ __launch_bounds__(320) void k_gemm2(const float* __restrict__ W2) {
    __shared__ float hs[32 * F1];     // 16 KB
    __shared__ float ws[F1 * F2];     // 20 KB
    int r0  = blockIdx.x * 32;
    int tid = threadIdx.x;
    for (int i = tid; i < F1 * F2; i += 320) ws[i] = W2[i];
    for (int i = tid; i < 32 * F1; i += 320) {
        int r = i >> 7;
        int gr = r0 + r;
        hs[i] = (gr < NNODES) ? g_h1a[(long)gr * F1 + (i & 127)] : 0.f;
    }
    __syncthreads();
    int c  = tid % 40;
    int rr = tid / 40;                // 0..7
    float acc[4];
#pragma unroll
    for (int i = 0; i < 4; i++) acc[i] = 0.f;
    for (int k = 0; k < F1; k++) {
        float w = ws[k * F2 + c];
#pragma unroll
        for (int i = 0; i < 4; i++)
            acc[i] += hs[(rr + i * 8) * F1 + k] * w;
    }
#pragma unroll
    for (int i = 0; i < 4; i++) {
        int gr = r0 + rr + i * 8;
        if (gr < NNODES) g_h2[(long)gr * F2 + c] = acc[i];
    }
}

// ---------------- attention coefficients, layer 2 ----------------
__global__ void k_coeff2(const float* __restrict__ att_s, const float* __restrict__ att_d) {
    int n = blockIdx.x * blockDim.x + threadIdx.x;
    if (n >= NNODES) return;
    const float* hp = &g_h2[(long)n * F2];
    float s = 0.f, d = 0.f;
#pragma unroll
    for (int c = 0; c < F2; c++) {
        float v = hp[c];
        s += v * att_s[c];
        d += v * att_d[c];
    }
    g_as2[n] = s;
    g_ad2[n] = d;
}

// ---------------- layer-2 aggregation + bias + log_softmax ----------------
__global__ void k_agg2(const float* __restrict__ b2, float* __restrict__ out) {
    int gtid = blockIdx.x * blockDim.x + threadIdx.x;
    int n    = gtid >> 5;
    int lane = threadIdx.x & 31;
    if (n >= NNODES) return;
    bool has2 = lane < 8;            // second channel = 32+lane
    int beg = g_rowptr[n], end = g_rowptr[n + 1];
    float adst = g_ad2[n];
    float m = -1e30f, s = 0.f, a0 = 0.f, a1 = 0.f;
    for (int j = beg; j < end; j++) {
        int src = g_csr[j];
        float e = g_as2[src] + adst;
        e = (e > 0.f) ? e : 0.2f * e;
        float mnew  = fmaxf(m, e);
        float scale = __expf(m - mnew);
        float w     = __expf(e - mnew);
        float v0 = g_h2[(long)src * F2 + lane];
        float v1 = has2 ? g_h2[(long)src * F2 + 32 + lane] : 0.f;
        s  = s  * scale + w;
        a0 = a0 * scale + w * v0;
        a1 = a1 * scale + w * v1;
        m = mnew;
    }
    float inv = 1.f / (s + 1e-16f);
    float x0 = a0 * inv + b2[lane];
    float x1 = has2 ? (a1 * inv + b2[32 + lane]) : -1e30f;
    // log_softmax over 40 values held by the warp
    float mx = fmaxf(x0, x1);
#pragma unroll
    for (int o = 16; o; o >>= 1) mx = fmaxf(mx, __shfl_xor_sync(0xFFFFFFFFu, mx, o));
    float se = __expf(x0 - mx) + (has2 ? __expf(x1 - mx) : 0.f);
#pragma unroll
    for (int o = 16; o; o >>= 1) se += __shfl_xor_sync(0xFFFFFFFFu, se, o);
    float lse = mx + logf(se);
    out[(long)n * F2 + lane] = x0 - lse;
    if (has2) out[(long)n * F2 + 32 + lane] = x1 - lse;
}

// ---------------- launch ----------------
extern "C" void kernel_launch(void* const* d_in, const int* in_sizes, int n_in,
                              void* d_out, int out_size) {
    const float* x   = (const float*)d_in[0];
    const int*   ei  = (const int*)d_in[1];        // JAX default: int64 request -> int32 array
    const float* W1  = (const float*)d_in[2];
    const float* as1 = (const float*)d_in[3];
    const float* ad1 = (const float*)d_in[4];
    const float* b1  = (const float*)d_in[5];
    const float* W2  = (const float*)d_in[6];
    const float* as2 = (const float*)d_in[7];
    const float* ad2 = (const float*)d_in[8];
    const float* b2  = (const float*)d_in[9];
    float*       out = (float*)d_out;

    int E    = in_sizes[1] / 2;
    if (E > EMAX) E = EMAX;
    int Etot = E + NNODES;
    int nb   = (NNODES + 1023) / 1024;

    k_zero_counts<<<(NNODES + 255) / 256, 256>>>();
    k_count<<<(Etot + 255) / 256, 256>>>(ei, E, Etot);
    k_scan1<<<nb, 1024>>>();
    k_scan2<<<1, 32>>>(nb);
    k_scan3<<<(NNODES + 255) / 256, 256>>>(Etot);
    k_fill<<<(Etot + 255) / 256, 256>>>(ei, E, Etot);

    k_gemm1<<<(NNODES + 63) / 64, 256>>>(x, W1);
    k_coeff1<<<(NNODES * H1N + 255) / 256, 256>>>(as1, ad1);
    k_agg1<<<(NNODES * 32 + 255) / 256, 256>>>(b1);

    k_gemm2<<<(NNODES + 31) / 32, 320>>>(W2);
    k_coeff2<<<(NNODES + 255) / 256, 256>>>(as2, ad2);
    k_agg2<<<(NNODES * 32 + 255) / 256, 256>>>(b2, out);
}

// round 3
// speedup vs baseline: 1.0059x; 1.0059x over previous
#include <cuda_runtime.h>
#include <cuda_bf16.h>

#define NNODES 50000
#define FIN    512
#define H1N    8
#define C1N    16
#define F1     128      // H1*C1
#define F2     40
#define EMAX   800000
#define ETOTMAX (EMAX + NNODES)

// ---------------- static scratch (no allocations allowed) ----------------
__device__ float g_h1 [NNODES * F1];   // layer1 GEMM output
__device__ float g_h1a[NNODES * F1];   // layer1 activated output
__device__ float g_as1[NNODES * H1N];
__device__ float g_ad1[NNODES * H1N];
__device__ float g_h2 [NNODES * F2];   // layer2 GEMM output
__device__ float g_as2[NNODES];
__device__ float g_ad2[NNODES];
__device__ int   g_counts[NNODES];
__device__ int   g_rowptr[NNODES + 1];
__device__ int   g_cursor[NNODES];
__device__ int   g_csr[ETOTMAX];       // src node per CSR slot (sorted by dst)
__device__ int   g_bsum[64];

// bf16 split operands for tensor-core GEMM1
__device__ __nv_bfloat16 g_Ah[NNODES * FIN];   // hi(x)
__device__ __nv_bfloat16 g_Am[NNODES * FIN];   // mid(x - hi)
__device__ __nv_bfloat16 g_Bth[F1 * FIN];      // hi(W1) transposed  [n][k]
__device__ __nv_bfloat16 g_Btm[F1 * FIN];      // mid(W1) transposed [n][k]

// ---------------- CSR build ----------------
__global__ void k_zero_counts() {
    int i = blockIdx.x * blockDim.x + threadIdx.x;
    if (i < NNODES) g_counts[i] = 0;
}

__global__ void k_count(const int* __restrict__ ei, int E, int Etot) {
    int i = blockIdx.x * blockDim.x + threadIdx.x;
    if (i >= Etot) return;
    int d = (i < E) ? ei[E + i] : (i - E);
    if (d < 0 || d >= NNODES) return;
    atomicAdd(&g_counts[d], 1);
}

__global__ void k_scan1() {
    __shared__ int tmp[1024];
    int t = threadIdx.x;
    int gid = blockIdx.x * 1024 + t;
    int v = (gid < NNODES) ? g_counts[gid] : 0;
    tmp[t] = v;
    __syncthreads();
    for (int off = 1; off < 1024; off <<= 1) {
        int x = (t >= off) ? tmp[t - off] : 0;
        __syncthreads();
        tmp[t] += x;
        __syncthreads();
    }
    if (gid < NNODES) g_rowptr[gid] = tmp[t] - v;   // exclusive within block
    if (t == 1023) g_bsum[blockIdx.x] = tmp[1023];
}

__global__ void k_scan2(int nb) {
    if (threadIdx.x == 0) {
        int acc = 0;
        for (int i = 0; i < nb; i++) { int x = g_bsum[i]; g_bsum[i] = acc; acc += x; }
    }
}

__global__ void k_scan3(int Etot) {
    int gid = blockIdx.x * blockDim.x + threadIdx.x;
    if (gid < NNODES) {
        int v = g_rowptr[gid] + g_bsum[gid >> 10];
        g_rowptr[gid] = v;
        g_cursor[gid] = v;
    }
    if (gid == 0) g_rowptr[NNODES] = Etot;
}

__global__ void k_fill(const int* __restrict__ ei, int E, int Etot) {
    int i = blockIdx.x * blockDim.x + threadIdx.x;
    if (i >= Etot) return;
    int s, d;
    if (i < E) { s = ei[i]; d = ei[E + i]; }
    else       { s = d = i - E; }
    if (d < 0 || d >= NNODES || s < 0 || s >= NNODES) return;
    int pos = atomicAdd(&g_cursor[d], 1);
    if (pos < ETOTMAX) g_csr[pos] = s;
}

// ---------------- bf16 split conversions ----------------
__global__ void k_splitA(const float* __restrict__ x) {
    long i = ((long)blockIdx.x * blockDim.x + threadIdx.x) * 4;
    if (i >= (long)NNODES * FIN) return;
    float4 v = *(const float4*)&x[i];
    __nv_bfloat16 h[4], m[4];
    float f[4] = {v.x, v.y, v.z, v.w};
#pragma unroll
    for (int j = 0; j < 4; j++) {
        h[j] = __float2bfloat16_rn(f[j]);
        m[j] = __float2bfloat16_rn(f[j] - __bfloat162float(h[j]));
    }
    *(uint2*)&g_Ah[i] = *(uint2*)h;
    *(uint2*)&g_Am[i] = *(uint2*)m;
}

__global__ void k_splitB(const float* __restrict__ W1) {
    int i = blockIdx.x * blockDim.x + threadIdx.x;   // over FIN*F1
    if (i >= FIN * F1) return;
    int k = i / F1, n = i % F1;
    float v = W1[i];
    __nv_bfloat16 h = __float2bfloat16_rn(v);
    __nv_bfloat16 m = __float2bfloat16_rn(v - __bfloat162float(h));
    g_Bth[n * FIN + k] = h;
    g_Btm[n * FIN + k] = m;
}

// ---------------- GEMM1 via mma.sync bf16 (3-way split) ----------------
// h1[50000x128] = x @ W1 computed as Ah*Bh + Ah*Bm + Am*Bh.
// BM=128, BN=128, BK=16. 256 threads = 8 warps in a 4(m) x 2(n) grid;
// warp tile 32x64 = 2 m16 x 8 n8 mma tiles.
// Smem layout: [row][16 halves] = 32B/row, two 16B chunks, chunk swizzled by
// (row>>2)&1 so every ldmatrix 8x8 read and every 16B store is conflict-free.

#define SWZ(row, chk) ((row) * 32 + (((chk) ^ (((row) >> 2) & 1)) << 4))

__device__ __forceinline__ void ldmx4(unsigned* r, unsigned addr) {
    asm volatile("ldmatrix.sync.aligned.m8n8.x4.shared.b16 {%0,%1,%2,%3}, [%4];"
                 : "=r"(r[0]), "=r"(r[1]), "=r"(r[2]), "=r"(r[3]) : "r"(addr));
}

__device__ __forceinline__ void mma16816(float* c, const unsigned* a, const unsigned* b) {
    asm volatile(
        "mma.sync.aligned.m16n8k16.row.col.f32.bf16.bf16.f32 "
        "{%0,%1,%2,%3}, {%4,%5,%6,%7}, {%8,%9}, {%0,%1,%2,%3};"
        : "+f"(c[0]), "+f"(c[1]), "+f"(c[2]), "+f"(c[3])
        : "r"(a[0]), "r"(a[1]), "r"(a[2]), "r"(a[3]), "r"(b[0]), "r"(b[1]));
}

__global__ __launch_bounds__(256) void k_gemm1_mma() {
    __shared__ __align__(16) unsigned char AsB[128 * 32];  // 4KB
    __shared__ __align__(16) unsigned char BsB[128 * 32];  // 4KB

    int tid  = threadIdx.x;
    int lane = tid & 31;
    int wid  = tid >> 5;
    int wr   = wid & 3;        // warp m index (0..3)
    int wc   = wid >> 2;       // warp n index (0..1)
    int bm   = blockIdx.x * 128;

    // global load mapping: each thread loads one 16B chunk of A and of B
    int lrow = tid >> 1;       // 0..127
    int lchk = tid & 1;        // chunk 0/1 (8 halves each)
    unsigned sA = (unsigned)__cvta_generic_to_shared(AsB) + SWZ(lrow, lchk);
    unsigned sB = (unsigned)__cvta_generic_to_shared(BsB) + SWZ(lrow, lchk);
    int grow = bm + lrow;
    bool aval = grow < NNODES;

    // ldmatrix source addresses (iteration-invariant)
    unsigned aBase = (unsigned)__cvta_generic_to_shared(AsB);
    unsigned bBase = (unsigned)__cvta_generic_to_shared(BsB);
    int sub = lane >> 3, r8 = lane & 7;
    unsigned aAddr[2], bAddr[4];
#pragma unroll
    for (int mt = 0; mt < 2; mt++) {
        int row = wr * 32 + mt * 16 + (sub & 1) * 8 + r8;
        aAddr[mt] = aBase + SWZ(row, sub >> 1);
    }
#pragma unroll
    for (int np = 0; np < 4; np++) {
        int row = wc * 64 + np * 16 + (sub >> 1) * 8 + r8;
        bAddr[np] = bBase + SWZ(row, sub & 1);
    }

    float acc[2][8][4];
#pragma unroll
    for (int mt = 0; mt < 2; mt++)
#pragma unroll
        for (int nt = 0; nt < 8; nt++)
#pragma unroll
            for (int j = 0; j < 4; j++) acc[mt][nt][j] = 0.f;

    const int NIT = 3 * (FIN / 16);   // 96

    uint4 pa = make_uint4(0, 0, 0, 0), pb;
    {   // prefetch iter 0: pass 0 (Ah, Bth), kk=0
        if (aval) pa = *(const uint4*)&g_Ah[(long)grow * FIN + lchk * 8];
        pb = *(const uint4*)&g_Bth[(long)lrow * FIN + lchk * 8];
    }

    for (int it = 0; it < NIT; it++) {
        *(uint4*)(AsB + (sA - aBase)) = pa;
        *(uint4*)(BsB + (sB - bBase)) = pb;
        __syncthreads();

        if (it + 1 < NIT) {
            int nit  = it + 1;
            int pass = nit >> 5;
            int kk   = nit & 31;
            const __nv_bfloat16* Asrc = (pass == 2) ? g_Am : g_Ah;
            const __nv_bfloat16* Bsrc = (pass == 1) ? g_Btm : g_Bth;
            pa = aval ? *(const uint4*)&Asrc[(long)grow * FIN + kk * 16 + lchk * 8]
                      : make_uint4(0, 0, 0, 0);
            pb = *(const uint4*)&Bsrc[(long)lrow * FIN + kk * 16 + lchk * 8];
        }

        unsigned af[2][4], bf[4][4];
#pragma unroll
        for (int mt = 0; mt < 2; mt++) ldmx4(af[mt], aAddr[mt]);
#pragma unroll
        for (int np = 0; np < 4; np++) ldmx4(bf[np], bAddr[np]);
#pragma unroll
        for (int mt = 0; mt < 2; mt++)
#pragma unroll
            for (int nt = 0; nt < 8; nt++)
                mma16816(acc[mt][nt], af[mt], &bf[nt >> 1][(nt & 1) * 2]);
        __syncthreads();
    }

    // epilogue
    int g = lane >> 2, t = lane & 3;
#pragma unroll
    for (int mt = 0; mt < 2; mt++) {
        int r0 = bm + wr * 32 + mt * 16 + g;
        int r1 = r0 + 8;
#pragma unroll
        for (int nt = 0; nt < 8; nt++) {
            int col = wc * 64 + nt * 8 + t * 2;
            if (r0 < NNODES)
                *(float2*)&g_h1[(long)r0 * F1 + col] = make_float2(acc[mt][nt][0], acc[mt][nt][1]);
            if (r1 < NNODES)
                *(float2*)&g_h1[(long)r1 * F1 + col] = make_float2(acc[mt][nt][2], acc[mt][nt][3]);
        }
    }
}

// ---------------- attention coefficients, layer 1 ----------------
__global__ void k_coeff1(const float* __restrict__ att_s, const float* __restrict__ att_d) {
    int i = blockIdx.x * blockDim.x + threadIdx.x;   // (n,h)
    if (i >= NNODES * H1N) return;
    int n = i >> 3, h = i & 7;
    const float* hp = &g_h1[(long)n * F1 + h * C1N];
    float s = 0.f, d = 0.f;
#pragma unroll
    for (int c = 0; c < C1N; c++) {
        float v = hp[c];
        s += v * att_s[h * C1N + c];
        d += v * att_d[h * C1N + c];
    }
    g_as1[i] = s;
    g_ad1[i] = d;
}

// ---------------- layer-1 aggregation: warp per node, online softmax ----------------
__global__ void k_agg1(const float* __restrict__ b1) {
    int gtid = blockIdx.x * blockDim.x + threadIdx.x;
    int n    = gtid >> 5;
    int lane = threadIdx.x & 31;
    if (n >= NNODES) return;
    int h = lane >> 2;               // head for this lane's 4 channels
    int beg = g_rowptr[n], end = g_rowptr[n + 1];
    float adst = g_ad1[n * H1N + h];
    float m = -1e30f, s = 0.f;
    float ax = 0.f, ay = 0.f, az = 0.f, aw = 0.f;
    for (int j = beg; j < end; j++) {
        int src = g_csr[j];
        float e = g_as1[src * H1N + h] + adst;
        e = (e > 0.f) ? e : 0.2f * e;
        float mnew  = fmaxf(m, e);
        float scale = __expf(m - mnew);
        float w     = __expf(e - mnew);
        float4 v = *(const float4*)&g_h1[(long)src * F1 + lane * 4];
        s  = s  * scale + w;
        ax = ax * scale + w * v.x;
        ay = ay * scale + w * v.y;
        az = az * scale + w * v.z;
        aw = aw * scale + w * v.w;
        m = mnew;
    }
    float inv = 1.f / (s + 1e-16f);
    float o[4];
    o[0] = ax * inv + b1[lane * 4 + 0];
    o[1] = ay * inv + b1[lane * 4 + 1];
    o[2] = az * inv + b1[lane * 4 + 2];
    o[3] = aw * inv + b1[lane * 4 + 3];
#pragma unroll
    for (int i = 0; i < 4; i++)
        o[i] = (o[i] > 0.f) ? o[i] : (__expf(o[i]) - 1.f);   // ELU
    *(float4*)&g_h1a[(long)n * F1 + lane * 4] = *(float4*)o;
}

// ---------------- GEMM2: h2 = h1a @ W2   (50000x128 @ 128x40) ----------------
__global__ __launch_bounds__(320) void k_gemm2(const float* __restrict__ W2) {
    __shared__ float hs[32 * F1];     // 16 KB
    __shared__ float ws[F1 * F2];     // 20 KB
    int r0  = blockIdx.x * 32;
    int tid = threadIdx.x;
    for (int i = tid; i < F1 * F2; i += 320) ws[i] = W2[i];
    for (int i = tid; i < 32 * F1; i += 320) {
        int r = i >> 7;
        int gr = r0 + r;
        hs[i] = (gr < NNODES) ? g_h1a[(long)gr * F1 + (i & 127)] : 0.f;
    }
    __syncthreads();
    int c  = tid % 40;
    int rr = tid / 40;                // 0..7
    float acc[4];
#pragma unroll
    for (int i = 0; i < 4; i++) acc[i] = 0.f;
    for (int k = 0; k < F1; k++) {
        float w = ws[k * F2 + c];
#pragma unroll
        for (int i = 0; i < 4; i++)
            acc[i] += hs[(rr + i * 8) * F1 + k] * w;
    }
#pragma unroll
    for (int i = 0; i < 4; i++) {
        int gr = r0 + rr + i * 8;
        if (gr < NNODES) g_h2[(long)gr * F2 + c] = acc[i];
    }
}

// ---------------- attention coefficients, layer 2 ----------------
__global__ void k_coeff2(const float* __restrict__ att_s, const float* __restrict__ att_d) {
    int n = blockIdx.x * blockDim.x + threadIdx.x;
    if (n >= NNODES) return;
    const float* hp = &g_h2[(long)n * F2];
    float s = 0.f, d = 0.f;
#pragma unroll
    for (int c = 0; c < F2; c++) {
        float v = hp[c];
        s += v * att_s[c];
        d += v * att_d[c];
    }
    g_as2[n] = s;
    g_ad2[n] = d;
}

// ---------------- layer-2 aggregation + bias + log_softmax ----------------
__global__ void k_agg2(const float* __restrict__ b2, float* __restrict__ out) {
    int gtid = blockIdx.x * blockDim.x + threadIdx.x;
    int n    = gtid >> 5;
    int lane = threadIdx.x & 31;
    if (n >= NNODES) return;
    bool has2 = lane < 8;            // second channel = 32+lane
    int beg = g_rowptr[n], end = g_rowptr[n + 1];
    float adst = g_ad2[n];
    float m = -1e30f, s = 0.f, a0 = 0.f, a1 = 0.f;
    for (int j = beg; j < end; j++) {
        int src = g_csr[j];
        float e = g_as2[src] + adst;
        e = (e > 0.f) ? e : 0.2f * e;
        float mnew  = fmaxf(m, e);
        float scale = __expf(m - mnew);
        float w     = __expf(e - mnew);
        float v0 = g_h2[(long)src * F2 + lane];
        float v1 = has2 ? g_h2[(long)src * F2 + 32 + lane] : 0.f;
        s  = s  * scale + w;
        a0 = a0 * scale + w * v0;
        a1 = a1 * scale + w * v1;
        m = mnew;
    }
    float inv = 1.f / (s + 1e-16f);
    float x0 = a0 * inv + b2[lane];
    float x1 = has2 ? (a1 * inv + b2[32 + lane]) : -1e30f;
    // log_softmax over 40 values held by the warp
    float mx = fmaxf(x0, x1);
#pragma unroll
    for (int o = 16; o; o >>= 1) mx = fmaxf(mx, __shfl_xor_sync(0xFFFFFFFFu, mx, o));
    float se = __expf(x0 - mx) + (has2 ? __expf(x1 - mx) : 0.f);
#pragma unroll
    for (int o = 16; o; o >>= 1) se += __shfl_xor_sync(0xFFFFFFFFu, se, o);
    float lse = mx + logf(se);
    out[(long)n * F2 + lane] = x0 - lse;
    if (has2) out[(long)n * F2 + 32 + lane] = x1 - lse;
}

// ---------------- launch ----------------
extern "C" void kernel_launch(void* const* d_in, const int* in_sizes, int n_in,
                              void* d_out, int out_size) {
    const float* x   = (const float*)d_in[0];
    const int*   ei  = (const int*)d_in[1];        // int32 in practice
    const float* W1  = (const float*)d_in[2];
    const float* as1 = (const float*)d_in[3];
    const float* ad1 = (const float*)d_in[4];
    const float* b1  = (const float*)d_in[5];
    const float* W2  = (const float*)d_in[6];
    const float* as2 = (const float*)d_in[7];
    const float* ad2 = (const float*)d_in[8];
    const float* b2  = (const float*)d_in[9];
    float*       out = (float*)d_out;

    int E    = in_sizes[1] / 2;
    if (E > EMAX) E = EMAX;
    int Etot = E + NNODES;
    int nb   = (NNODES + 1023) / 1024;

    // operand conversion for tensor-core GEMM1
    k_splitA<<<(NNODES * FIN / 4 + 255) / 256, 256>>>(x);
    k_splitB<<<(FIN * F1 + 255) / 256, 256>>>(W1);

    // CSR build (overlaps conceptually; stream-serialized is fine)
    k_zero_counts<<<(NNODES + 255) / 256, 256>>>();
    k_count<<<(Etot + 255) / 256, 256>>>(ei, E, Etot);
    k_scan1<<<nb, 1024>>>();
    k_scan2<<<1, 32>>>(nb);
    k_scan3<<<(NNODES + 255) / 256, 256>>>(Etot);
    k_fill<<<(Etot + 255) / 256, 256>>>(ei, E, Etot);

    k_gemm1_mma<<<(NNODES + 127) / 128, 256>>>();
    k_coeff1<<<(NNODES * H1N + 255) / 256, 256>>>(as1, ad1);
    k_agg1<<<(NNODES * 32 + 255) / 256, 256>>>(b1);

    k_gemm2<<<(NNODES + 31) / 32, 320>>>(W2);
    k_coeff2<<<(NNODES + 255) / 256, 256>>>(as2, ad2);
    k_agg2<<<(NNODES * 32 + 255) / 256, 256>>>(b2, out);
}

// round 4
// speedup vs baseline: 1.1280x; 1.1213x over previous
#include <cuda_runtime.h>
#include <cuda_bf16.h>

#define NNODES 50000
#define FIN    512
#define H1N    8
#define C1N    16
#define F1     128      // H1*C1
#define F2     40
#define EMAX   800000
#define ETOTMAX (EMAX + NNODES)

// ---------------- static scratch ----------------
__device__ float g_h1 [NNODES * F1];
__device__ float g_h1a[NNODES * F1];
__device__ float g_as1[NNODES * H1N];
__device__ float g_ad1[NNODES * H1N];
__device__ float g_h2 [NNODES * F2];
__device__ float g_as2[NNODES];
__device__ float g_ad2[NNODES];
__device__ int   g_counts[NNODES];
__device__ int   g_rowptr[NNODES + 1];
__device__ int   g_cursor[NNODES];
__device__ int   g_csr[ETOTMAX];
__device__ int   g_bsum[64];

__device__ __nv_bfloat16 g_Ah[NNODES * FIN];
__device__ __nv_bfloat16 g_Am[NNODES * FIN];
__device__ __nv_bfloat16 g_Bth[F1 * FIN];
__device__ __nv_bfloat16 g_Btm[F1 * FIN];

// ---------------- CSR build ----------------
__global__ void k_zero_counts() {
    int i = blockIdx.x * blockDim.x + threadIdx.x;
    if (i < NNODES) g_counts[i] = 0;
}

__global__ void k_count(const int* __restrict__ ei, int E, int Etot) {
    int i = blockIdx.x * blockDim.x + threadIdx.x;
    if (i >= Etot) return;
    int d = (i < E) ? ei[E + i] : (i - E);
    if (d < 0 || d >= NNODES) return;
    atomicAdd(&g_counts[d], 1);
}

__global__ void k_scan1() {
    __shared__ int tmp[1024];
    int t = threadIdx.x;
    int gid = blockIdx.x * 1024 + t;
    int v = (gid < NNODES) ? g_counts[gid] : 0;
    tmp[t] = v;
    __syncthreads();
    for (int off = 1; off < 1024; off <<= 1) {
        int x = (t >= off) ? tmp[t - off] : 0;
        __syncthreads();
        tmp[t] += x;
        __syncthreads();
    }
    if (gid < NNODES) g_rowptr[gid] = tmp[t] - v;
    if (t == 1023) g_bsum[blockIdx.x] = tmp[1023];
}

__global__ void k_scan2(int nb) {
    if (threadIdx.x == 0) {
        int acc = 0;
        for (int i = 0; i < nb; i++) { int x = g_bsum[i]; g_bsum[i] = acc; acc += x; }
    }
}

__global__ void k_scan3(int Etot) {
    int gid = blockIdx.x * blockDim.x + threadIdx.x;
    if (gid < NNODES) {
        int v = g_rowptr[gid] + g_bsum[gid >> 10];
        g_rowptr[gid] = v;
        g_cursor[gid] = v;
    }
    if (gid == 0) g_rowptr[NNODES] = Etot;
}

__global__ void k_fill(const int* __restrict__ ei, int E, int Etot) {
    int i = blockIdx.x * blockDim.x + threadIdx.x;
    if (i >= Etot) return;
    int s, d;
    if (i < E) { s = ei[i]; d = ei[E + i]; }
    else       { s = d = i - E; }
    if (d < 0 || d >= NNODES || s < 0 || s >= NNODES) return;
    int pos = atomicAdd(&g_cursor[d], 1);
    if (pos < ETOTMAX) g_csr[pos] = s;
}

// ---------------- bf16 split conversions ----------------
__global__ void k_splitA(const float* __restrict__ x) {
    long i = ((long)blockIdx.x * blockDim.x + threadIdx.x) * 4;
    if (i >= (long)NNODES * FIN) return;
    float4 v = *(const float4*)&x[i];
    __nv_bfloat16 h[4], m[4];
    float f[4] = {v.x, v.y, v.z, v.w};
#pragma unroll
    for (int j = 0; j < 4; j++) {
        h[j] = __float2bfloat16_rn(f[j]);
        m[j] = __float2bfloat16_rn(f[j] - __bfloat162float(h[j]));
    }
    *(uint2*)&g_Ah[i] = *(uint2*)h;
    *(uint2*)&g_Am[i] = *(uint2*)m;
}

__global__ void k_splitB(const float* __restrict__ W1) {
    int i = blockIdx.x * blockDim.x + threadIdx.x;
    if (i >= FIN * F1) return;
    int k = i / F1, n = i % F1;
    float v = W1[i];
    __nv_bfloat16 h = __float2bfloat16_rn(v);
    __nv_bfloat16 m = __float2bfloat16_rn(v - __bfloat162float(h));
    g_Bth[n * FIN + k] = h;
    g_Btm[n * FIN + k] = m;
}

// ---------------- GEMM1 via mma.sync bf16, BK=32, double-buffered cp.async --
// smem row = 32 halves = 64B = 4 chunks of 16B; chunk swizzled by (row>>1)&3.
#define SWZ32(row, chk) ((row) * 64 + (((chk) ^ (((row) >> 1) & 3)) << 4))

__device__ __forceinline__ void ldmx4(unsigned* r, unsigned addr) {
    asm volatile("ldmatrix.sync.aligned.m8n8.x4.shared.b16 {%0,%1,%2,%3}, [%4];"
                 : "=r"(r[0]), "=r"(r[1]), "=r"(r[2]), "=r"(r[3]) : "r"(addr));
}

__device__ __forceinline__ void mma16816(float* c, const unsigned* a, const unsigned* b) {
    asm volatile(
        "mma.sync.aligned.m16n8k16.row.col.f32.bf16.bf16.f32 "
        "{%0,%1,%2,%3}, {%4,%5,%6,%7}, {%8,%9}, {%0,%1,%2,%3};"
        : "+f"(c[0]), "+f"(c[1]), "+f"(c[2]), "+f"(c[3])
        : "r"(a[0]), "r"(a[1]), "r"(a[2]), "r"(a[3]), "r"(b[0]), "r"(b[1]));
}

__device__ __forceinline__ void cpasync16(unsigned saddr, const void* gaddr, int sz) {
    asm volatile("cp.async.cg.shared.global [%0], [%1], 16, %2;"
                 :: "r"(saddr), "l"(gaddr), "r"(sz));
}

__global__ __launch_bounds__(256) void k_gemm1_mma() {
    __shared__ __align__(16) unsigned char AsB[2][128 * 64];  // 8KB x2
    __shared__ __align__(16) unsigned char BsB[2][128 * 64];  // 8KB x2

    int tid  = threadIdx.x;
    int lane = tid & 31;
    int wid  = tid >> 5;
    int wr   = wid & 3;
    int wc   = wid >> 2;
    int bm   = blockIdx.x * 128;

    // per-thread load slots: rows (tid>>2) and 64+(tid>>2), chunk tid&3
    int lrow = tid >> 2;          // 0..63
    int lchk = tid & 3;
    unsigned aBase = (unsigned)__cvta_generic_to_shared(&AsB[0][0]);
    unsigned bBase = (unsigned)__cvta_generic_to_shared(&BsB[0][0]);
    unsigned sAo0 = SWZ32(lrow, lchk), sAo1 = SWZ32(lrow + 64, lchk);
    int gr0 = bm + lrow, gr1 = bm + lrow + 64;
    int sz0 = (gr0 < NNODES) ? 16 : 0;
    int sz1 = (gr1 < NNODES) ? 16 : 0;

    // ldmatrix offsets (within one buffer)
    int sub = lane >> 3, r8 = lane & 7;
    unsigned aOff[2][2], bOff[4][2];
#pragma unroll
    for (int mt = 0; mt < 2; mt++) {
        int row = wr * 32 + mt * 16 + (sub & 1) * 8 + r8;
#pragma unroll
        for (int ks = 0; ks < 2; ks++)
            aOff[mt][ks] = SWZ32(row, (sub >> 1) + 2 * ks);
    }
#pragma unroll
    for (int np = 0; np < 4; np++) {
        int row = wc * 64 + np * 16 + (sub >> 1) * 8 + r8;
#pragma unroll
        for (int ks = 0; ks < 2; ks++)
            bOff[np][ks] = SWZ32(row, (sub & 1) + 2 * ks);
    }

    float acc[2][8][4];
#pragma unroll
    for (int mt = 0; mt < 2; mt++)
#pragma unroll
        for (int nt = 0; nt < 8; nt++)
#pragma unroll
            for (int j = 0; j < 4; j++) acc[mt][nt][j] = 0.f;

    const int NIT = 3 * (FIN / 32);   // 48

    // issue loads for iteration it into buffer b
    auto issue = [&](int it, int b) {
        int pass = it >> 4;
        int koff = (it & 15) * 32;
        const __nv_bfloat16* Asrc = (pass == 2) ? g_Am : g_Ah;
        const __nv_bfloat16* Bsrc = (pass == 1) ? g_Btm : g_Bth;
        unsigned ab = aBase + b * (128 * 64);
        unsigned bb = bBase + b * (128 * 64);
        cpasync16(ab + sAo0, &Asrc[(long)gr0 * FIN + koff + lchk * 8], sz0);
        cpasync16(ab + sAo1, &Asrc[(long)gr1 * FIN + koff + lchk * 8], sz1);
        cpasync16(bb + SWZ32(lrow, lchk),      &Bsrc[(long)lrow * FIN + koff + lchk * 8], 16);
        cpasync16(bb + SWZ32(lrow + 64, lchk), &Bsrc[(long)(lrow + 64) * FIN + koff + lchk * 8], 16);
    };

    issue(0, 0);
    asm volatile("cp.async.commit_group;" ::);

    for (int it = 0; it < NIT; it++) {
        int buf = it & 1;
        if (it + 1 < NIT) {
            issue(it + 1, buf ^ 1);
            asm volatile("cp.async.commit_group;" ::);
            asm volatile("cp.async.wait_group 1;" ::);
        } else {
            asm volatile("cp.async.wait_group 0;" ::);
        }
        __syncthreads();

        unsigned ab = aBase + buf * (128 * 64);
        unsigned bb = bBase + buf * (128 * 64);
#pragma unroll
        for (int ks = 0; ks < 2; ks++) {
            unsigned af[2][4], bf[4][4];
#pragma unroll
            for (int mt = 0; mt < 2; mt++) ldmx4(af[mt], ab + aOff[mt][ks]);
#pragma unroll
            for (int np = 0; np < 4; np++) ldmx4(bf[np], bb + bOff[np][ks]);
#pragma unroll
            for (int mt = 0; mt < 2; mt++)
#pragma unroll
                for (int nt = 0; nt < 8; nt++)
                    mma16816(acc[mt][nt], af[mt], &bf[nt >> 1][(nt & 1) * 2]);
        }
        __syncthreads();
    }

    int g = lane >> 2, t = lane & 3;
#pragma unroll
    for (int mt = 0; mt < 2; mt++) {
        int r0 = bm + wr * 32 + mt * 16 + g;
        int r1 = r0 + 8;
#pragma unroll
        for (int nt = 0; nt < 8; nt++) {
            int col = wc * 64 + nt * 8 + t * 2;
            if (r0 < NNODES)
                *(float2*)&g_h1[(long)r0 * F1 + col] = make_float2(acc[mt][nt][0], acc[mt][nt][1]);
            if (r1 < NNODES)
                *(float2*)&g_h1[(long)r1 * F1 + col] = make_float2(acc[mt][nt][2], acc[mt][nt][3]);
        }
    }
}

// ---------------- attention coefficients, layer 1 ----------------
__global__ void k_coeff1(const float* __restrict__ att_s, const float* __restrict__ att_d) {
    int i = blockIdx.x * blockDim.x + threadIdx.x;
    if (i >= NNODES * H1N) return;
    int n = i >> 3, h = i & 7;
    const float* hp = &g_h1[(long)n * F1 + h * C1N];
    float s = 0.f, d = 0.f;
#pragma unroll
    for (int c = 0; c < C1N; c++) {
        float v = hp[c];
        s += v * att_s[h * C1N + c];
        d += v * att_d[h * C1N + c];
    }
    g_as1[i] = s;
    g_ad1[i] = d;
}

// ---------------- layer-1 aggregation: warp/node, pipelined online softmax --
__global__ void k_agg1(const float* __restrict__ b1) {
    int gtid = blockIdx.x * blockDim.x + threadIdx.x;
    int n    = gtid >> 5;
    int lane = threadIdx.x & 31;
    if (n >= NNODES) return;
    int h = lane >> 2;
    int beg = g_rowptr[n], end = g_rowptr[n + 1];
    float adst = g_ad1[n * H1N + h];
    float m = -1e30f, s = 0.f;
    float ax = 0.f, ay = 0.f, az = 0.f, aw = 0.f;

    int   s_p2 = (beg + 1 < end) ? __ldg(&g_csr[beg + 1]) : 0;
    float e_p1 = 0.f;
    float4 v_p1 = make_float4(0.f, 0.f, 0.f, 0.f);
    if (beg < end) {
        int s0 = __ldg(&g_csr[beg]);
        e_p1 = g_as1[s0 * H1N + h];
        v_p1 = *(const float4*)&g_h1[(long)s0 * F1 + lane * 4];
    }
    for (int j = beg; j < end; j++) {
        float  e_c = e_p1 + adst;
        float4 v   = v_p1;
        int s_nxt = s_p2;
        if (j + 2 < end) s_p2 = __ldg(&g_csr[j + 2]);
        if (j + 1 < end) {
            e_p1 = g_as1[s_nxt * H1N + h];
            v_p1 = *(const float4*)&g_h1[(long)s_nxt * F1 + lane * 4];
        }
        float e = (e_c > 0.f) ? e_c : 0.2f * e_c;
        float mnew  = fmaxf(m, e);
        float scale = __expf(m - mnew);
        float w     = __expf(e - mnew);
        s  = s  * scale + w;
        ax = ax * scale + w * v.x;
        ay = ay * scale + w * v.y;
        az = az * scale + w * v.z;
        aw = aw * scale + w * v.w;
        m = mnew;
    }
    float inv = 1.f / (s + 1e-16f);
    float o[4];
    o[0] = ax * inv + b1[lane * 4 + 0];
    o[1] = ay * inv + b1[lane * 4 + 1];
    o[2] = az * inv + b1[lane * 4 + 2];
    o[3] = aw * inv + b1[lane * 4 + 3];
#pragma unroll
    for (int i = 0; i < 4; i++)
        o[i] = (o[i] > 0.f) ? o[i] : (__expf(o[i]) - 1.f);
    *(float4*)&g_h1a[(long)n * F1 + lane * 4] = *(float4*)o;
}

// ---------------- GEMM2: h2 = h1a @ W2 (float4 LDS, padded stride) ---------
#define HP 132   // padded row stride (floats)
__global__ __launch_bounds__(320) void k_gemm2(const float* __restrict__ W2) {
    __shared__ float hs [32 * HP];    // ~16.9 KB
    __shared__ float wst[40 * HP];    // ~21.1 KB, transposed [c][k]
    int r0  = blockIdx.x * 32;
    int tid = threadIdx.x;
    for (int i = tid; i < 40 * F1; i += 320) {
        int c = i >> 7, k = i & 127;
        wst[c * HP + k] = W2[k * F2 + c];
    }
    for (int i = tid; i < 32 * F1; i += 320) {
        int r = i >> 7, k = i & 127;
        int gr = r0 + r;
        hs[r * HP + k] = (gr < NNODES) ? g_h1a[(long)gr * F1 + k] : 0.f;
    }
    __syncthreads();
    int c  = tid % 40;
    int rr = tid / 40;
    float acc[4] = {0.f, 0.f, 0.f, 0.f};
    for (int k4 = 0; k4 < F1 / 4; k4++) {
        float4 w = *(float4*)&wst[c * HP + k4 * 4];
#pragma unroll
        for (int i = 0; i < 4; i++) {
            float4 hv = *(float4*)&hs[(rr + i * 8) * HP + k4 * 4];
            acc[i] += w.x * hv.x + w.y * hv.y + w.z * hv.z + w.w * hv.w;
        }
    }
#pragma unroll
    for (int i = 0; i < 4; i++) {
        int gr = r0 + rr + i * 8;
        if (gr < NNODES) g_h2[(long)gr * F2 + c] = acc[i];
    }
}

// ---------------- attention coefficients, layer 2 ----------------
__global__ void k_coeff2(const float* __restrict__ att_s, const float* __restrict__ att_d) {
    int n = blockIdx.x * blockDim.x + threadIdx.x;
    if (n >= NNODES) return;
    const float* hp = &g_h2[(long)n * F2];
    float s = 0.f, d = 0.f;
#pragma unroll
    for (int c = 0; c < F2; c++) {
        float v = hp[c];
        s += v * att_s[c];
        d += v * att_d[c];
    }
    g_as2[n] = s;
    g_ad2[n] = d;
}

// ---------------- layer-2 aggregation + bias + log_softmax ----------------
__global__ void k_agg2(const float* __restrict__ b2, float* __restrict__ out) {
    int gtid = blockIdx.x * blockDim.x + threadIdx.x;
    int n    = gtid >> 5;
    int lane = threadIdx.x & 31;
    if (n >= NNODES) return;
    bool has2 = lane < 8;
    int beg = g_rowptr[n], end = g_rowptr[n + 1];
    float adst = g_ad2[n];
    float m = -1e30f, s = 0.f, a0 = 0.f, a1 = 0.f;

    int   s_p2 = (beg + 1 < end) ? __ldg(&g_csr[beg + 1]) : 0;
    float e_p1 = 0.f, v0_p = 0.f, v1_p = 0.f;
    if (beg < end) {
        int s0 = __ldg(&g_csr[beg]);
        e_p1 = g_as2[s0];
        v0_p = g_h2[(long)s0 * F2 + lane];
        v1_p = has2 ? g_h2[(long)s0 * F2 + 32 + lane] : 0.f;
    }
    for (int j = beg; j < end; j++) {
        float e_c = e_p1 + adst;
        float v0 = v0_p, v1 = v1_p;
        int s_nxt = s_p2;
        if (j + 2 < end) s_p2 = __ldg(&g_csr[j + 2]);
        if (j + 1 < end) {
            e_p1 = g_as2[s_nxt];
            v0_p = g_h2[(long)s_nxt * F2 + lane];
            v1_p = has2 ? g_h2[(long)s_nxt * F2 + 32 + lane] : 0.f;
        }
        float e = (e_c > 0.f) ? e_c : 0.2f * e_c;
        float mnew  = fmaxf(m, e);
        float scale = __expf(m - mnew);
        float w     = __expf(e - mnew);
        s  = s  * scale + w;
        a0 = a0 * scale + w * v0;
        a1 = a1 * scale + w * v1;
        m = mnew;
    }
    float inv = 1.f / (s + 1e-16f);
    float x0 = a0 * inv + b2[lane];
    float x1 = has2 ? (a1 * inv + b2[32 + lane]) : -1e30f;
    float mx = fmaxf(x0, x1);
#pragma unroll
    for (int o = 16; o; o >>= 1) mx = fmaxf(mx, __shfl_xor_sync(0xFFFFFFFFu, mx, o));
    float se = __expf(x0 - mx) + (has2 ? __expf(x1 - mx) : 0.f);
#pragma unroll
    for (int o = 16; o; o >>= 1) se += __shfl_xor_sync(0xFFFFFFFFu, se, o);
    float lse = mx + logf(se);
    out[(long)n * F2 + lane] = x0 - lse;
    if (has2) out[(long)n * F2 + 32 + lane] = x1 - lse;
}

// ---------------- launch ----------------
extern "C" void kernel_launch(void* const* d_in, const int* in_sizes, int n_in,
                              void* d_out, int out_size) {
    const float* x   = (const float*)d_in[0];
    const int*   ei  = (const int*)d_in[1];
    const float* W1  = (const float*)d_in[2];
    const float* as1 = (const float*)d_in[3];
    const float* ad1 = (const float*)d_in[4];
    const float* b1  = (const float*)d_in[5];
    const float* W2  = (const float*)d_in[6];
    const float* as2 = (const float*)d_in[7];
    const float* ad2 = (const float*)d_in[8];
    const float* b2  = (const float*)d_in[9];
    float*       out = (float*)d_out;

    int E    = in_sizes[1] / 2;
    if (E > EMAX) E = EMAX;
    int Etot = E + NNODES;
    int nb   = (NNODES + 1023) / 1024;

    // ordered so launch #5 (after ncu -s 5) is k_gemm1_mma
    k_splitA<<<(NNODES * FIN / 4 + 255) / 256, 256>>>(x);          // 0
    k_splitB<<<(FIN * F1 + 255) / 256, 256>>>(W1);                 // 1
    k_zero_counts<<<(NNODES + 255) / 256, 256>>>();                // 2
    k_count<<<(Etot + 255) / 256, 256>>>(ei, E, Etot);             // 3
    k_scan1<<<nb, 1024>>>();                                       // 4
    k_gemm1_mma<<<(NNODES + 127) / 128, 256>>>();                  // 5  <- profiled
    k_scan2<<<1, 32>>>(nb);                                        // 6
    k_scan3<<<(NNODES + 255) / 256, 256>>>(Etot);                  // 7
    k_fill<<<(Etot + 255) / 256, 256>>>(ei, E, Etot);              // 8
    k_coeff1<<<(NNODES * H1N + 255) / 256, 256>>>(as1, ad1);       // 9
    k_agg1<<<(NNODES * 32 + 255) / 256, 256>>>(b1);                // 10
    k_gemm2<<<(NNODES + 31) / 32, 320>>>(W2);                      // 11
    k_coeff2<<<(NNODES + 255) / 256, 256>>>(as2, ad2);             // 12
    k_agg2<<<(NNODES * 32 + 255) / 256, 256>>>(b2, out);           // 13
}

// round 5
// speedup vs baseline: 1.2645x; 1.1211x over previous
#include <cuda_runtime.h>
#include <cuda_bf16.h>

#define NNODES 50000
#define FIN    512
#define H1N    8
#define C1N    16
#define F1     128      // H1*C1
#define F2     40
#define EMAX   800000
#define ETOTMAX (EMAX + NNODES)

// ---------------- static scratch ----------------
__device__ float g_h1 [NNODES * F1];
__device__ float g_h1a[NNODES * F1];
__device__ float g_as1[NNODES * H1N];
__device__ float g_ad1[NNODES * H1N];
__device__ float g_h2 [NNODES * F2];
__device__ float g_as2[NNODES];
__device__ float g_ad2[NNODES];
__device__ int   g_counts[NNODES];
__device__ int   g_rowptr[NNODES + 1];
__device__ int   g_cursor[NNODES];
__device__ int   g_csr[ETOTMAX];
__device__ int   g_bsum[64];

__device__ __nv_bfloat16 g_Bth[F1 * FIN];   // hi(W1) transposed  [n][k]
__device__ __nv_bfloat16 g_Btm[F1 * FIN];   // mid(W1) transposed [n][k]

// ---------------- CSR build ----------------
__global__ void k_zero_counts() {
    int i = blockIdx.x * blockDim.x + threadIdx.x;
    if (i < NNODES) g_counts[i] = 0;
}

__global__ void k_count(const int* __restrict__ ei, int E, int Etot) {
    int i = blockIdx.x * blockDim.x + threadIdx.x;
    if (i >= Etot) return;
    int d = (i < E) ? ei[E + i] : (i - E);
    if (d < 0 || d >= NNODES) return;
    atomicAdd(&g_counts[d], 1);
}

__global__ void k_scan1() {
    __shared__ int tmp[1024];
    int t = threadIdx.x;
    int gid = blockIdx.x * 1024 + t;
    int v = (gid < NNODES) ? g_counts[gid] : 0;
    tmp[t] = v;
    __syncthreads();
    for (int off = 1; off < 1024; off <<= 1) {
        int x = (t >= off) ? tmp[t - off] : 0;
        __syncthreads();
        tmp[t] += x;
        __syncthreads();
    }
    if (gid < NNODES) g_rowptr[gid] = tmp[t] - v;
    if (t == 1023) g_bsum[blockIdx.x] = tmp[1023];
}

__global__ void k_scan2(int nb) {
    if (threadIdx.x == 0) {
        int acc = 0;
        for (int i = 0; i < nb; i++) { int x = g_bsum[i]; g_bsum[i] = acc; acc += x; }
    }
}

__global__ void k_scan3(int Etot) {
    int gid = blockIdx.x * blockDim.x + threadIdx.x;
    if (gid < NNODES) {
        int v = g_rowptr[gid] + g_bsum[gid >> 10];
        g_rowptr[gid] = v;
        g_cursor[gid] = v;
    }
    if (gid == 0) g_rowptr[NNODES] = Etot;
}

__global__ void k_fill(const int* __restrict__ ei, int E, int Etot) {
    int i = blockIdx.x * blockDim.x + threadIdx.x;
    if (i >= Etot) return;
    int s, d;
    if (i < E) { s = ei[i]; d = ei[E + i]; }
    else       { s = d = i - E; }
    if (d < 0 || d >= NNODES || s < 0 || s >= NNODES) return;
    int pos = atomicAdd(&g_cursor[d], 1);
    if (pos < ETOTMAX) g_csr[pos] = s;
}

// ---------------- bf16 split of W1 (tiny: 128KB) ----------------
__global__ void k_splitB(const float* __restrict__ W1) {
    int i = blockIdx.x * blockDim.x + threadIdx.x;
    if (i >= FIN * F1) return;
    int k = i / F1, n = i % F1;
    float v = W1[i];
    __nv_bfloat16 h = __float2bfloat16_rn(v);
    __nv_bfloat16 m = __float2bfloat16_rn(v - __bfloat162float(h));
    g_Bth[n * FIN + k] = h;
    g_Btm[n * FIN + k] = m;
}

// ---------------- GEMM1: single K-loop, in-register fp32->bf16 split -------
// h1 = x@W1 via Ah*Bh + Ah*Bm + Am*Bh, fused per K-tile.
// BM=128, BN=128, BK=32, 256 threads = 8 warps (4m x 2n), warp tile 32x64.
// smem row = 32 halves = 64B = 4x16B chunks, chunk swizzled by (row>>1)&3.
#define SWZ32(row, chk) ((row) * 64 + (((chk) ^ (((row) >> 1) & 3)) << 4))
#define TILEB 8192   // one 128x32 bf16 tile

__device__ __forceinline__ void ldmx4(unsigned* r, unsigned addr) {
    asm volatile("ldmatrix.sync.aligned.m8n8.x4.shared.b16 {%0,%1,%2,%3}, [%4];"
                 : "=r"(r[0]), "=r"(r[1]), "=r"(r[2]), "=r"(r[3]) : "r"(addr));
}

__device__ __forceinline__ void mma16816(float* c, const unsigned* a, const unsigned* b) {
    asm volatile(
        "mma.sync.aligned.m16n8k16.row.col.f32.bf16.bf16.f32 "
        "{%0,%1,%2,%3}, {%4,%5,%6,%7}, {%8,%9}, {%0,%1,%2,%3};"
        : "+f"(c[0]), "+f"(c[1]), "+f"(c[2]), "+f"(c[3])
        : "r"(a[0]), "r"(a[1]), "r"(a[2]), "r"(a[3]), "r"(b[0]), "r"(b[1]));
}

__device__ __forceinline__ void cpasync16(unsigned saddr, const void* gaddr) {
    asm volatile("cp.async.cg.shared.global [%0], [%1], 16;"
                 :: "r"(saddr), "l"(gaddr));
}

extern __shared__ __align__(16) unsigned char dynsmem[];

__global__ __launch_bounds__(256) void k_gemm1_mma(const float* __restrict__ X) {
    // dynamic smem: AH[2], AM[2], BH[2], BM[2] tiles of 8KB each = 64KB
    const int AH = 0, AM = 2 * TILEB, BH = 4 * TILEB, BMo = 6 * TILEB;
    unsigned base = (unsigned)__cvta_generic_to_shared(dynsmem);

    int tid  = threadIdx.x;
    int lane = tid & 31;
    int wid  = tid >> 5;
    int wr   = wid & 3;
    int wc   = wid >> 2;
    int bm   = blockIdx.x * 128;

    // A fp32 load mapping: 8 threads/row, 4 floats each; 4 rows/thread (+32 apart)
    int arow = tid >> 3;          // 0..31
    int acol = (tid & 7) * 4;     // 0..28
    bool av[4];
    long gA[4];
#pragma unroll
    for (int i = 0; i < 4; i++) {
        int r = bm + arow + 32 * i;
        av[i] = r < NNODES;
        gA[i] = (long)r * FIN;
    }
    unsigned aStOff = SWZ32(arow, acol >> 3) + ((acol & 4) << 1);  // +8B for odd half-chunk

    // B cp.async mapping
    int lrow = tid >> 2, lchk = tid & 3;
    unsigned sBo0 = SWZ32(lrow, lchk), sBo1 = SWZ32(lrow + 64, lchk);

    // ldmatrix offsets (within one tile)
    int sub = lane >> 3, r8 = lane & 7;
    unsigned aOff[2][2], bOff[4][2];
#pragma unroll
    for (int mt = 0; mt < 2; mt++) {
        int row = wr * 32 + mt * 16 + (sub & 1) * 8 + r8;
#pragma unroll
        for (int ks = 0; ks < 2; ks++)
            aOff[mt][ks] = SWZ32(row, (sub >> 1) + 2 * ks);
    }
#pragma unroll
    for (int np = 0; np < 4; np++) {
        int row = wc * 64 + np * 16 + (sub >> 1) * 8 + r8;
#pragma unroll
        for (int ks = 0; ks < 2; ks++)
            bOff[np][ks] = SWZ32(row, (sub & 1) + 2 * ks);
    }

    float acc[2][8][4];
#pragma unroll
    for (int mt = 0; mt < 2; mt++)
#pragma unroll
        for (int nt = 0; nt < 8; nt++)
#pragma unroll
            for (int j = 0; j < 4; j++) acc[mt][nt][j] = 0.f;

    const int NIT = FIN / 32;   // 16

    auto issueB = [&](int it, int b) {
        int koff = it * 32;
        cpasync16(base + BH  + b * TILEB + sBo0, &g_Bth[(long)lrow * FIN + koff + lchk * 8]);
        cpasync16(base + BH  + b * TILEB + sBo1, &g_Bth[(long)(lrow + 64) * FIN + koff + lchk * 8]);
        cpasync16(base + BMo + b * TILEB + sBo0, &g_Btm[(long)lrow * FIN + koff + lchk * 8]);
        cpasync16(base + BMo + b * TILEB + sBo1, &g_Btm[(long)(lrow + 64) * FIN + koff + lchk * 8]);
    };
    auto loadA = [&](int it, float4* ra) {
        int koff = it * 32 + acol;
#pragma unroll
        for (int i = 0; i < 4; i++)
            ra[i] = av[i] ? *(const float4*)&X[gA[i] + koff]
                          : make_float4(0.f, 0.f, 0.f, 0.f);
    };

    float4 ra[4];
    issueB(0, 0);
    asm volatile("cp.async.commit_group;" ::);
    loadA(0, ra);

    for (int it = 0; it < NIT; it++) {
        int buf = it & 1;
        // convert + store A tile (hi & mid)
#pragma unroll
        for (int i = 0; i < 4; i++) {
            float f[4] = {ra[i].x, ra[i].y, ra[i].z, ra[i].w};
            __nv_bfloat16 h[4], m[4];
#pragma unroll
            for (int j = 0; j < 4; j++) {
                h[j] = __float2bfloat16_rn(f[j]);
                m[j] = __float2bfloat16_rn(f[j] - __bfloat162float(h[j]));
            }
            unsigned off = aStOff + 32 * i * 64;   // row += 32
            *(uint2*)(dynsmem + AH + buf * TILEB + off) = *(uint2*)h;
            *(uint2*)(dynsmem + AM + buf * TILEB + off) = *(uint2*)m;
        }
        if (it + 1 < NIT) {
            loadA(it + 1, ra);
            issueB(it + 1, buf ^ 1);
            asm volatile("cp.async.commit_group;" ::);
            asm volatile("cp.async.wait_group 1;" ::);
        } else {
            asm volatile("cp.async.wait_group 0;" ::);
        }
        __syncthreads();

        unsigned ah = base + AH  + buf * TILEB;
        unsigned am = base + AM  + buf * TILEB;
        unsigned bh = base + BH  + buf * TILEB;
        unsigned bmm = base + BMo + buf * TILEB;
#pragma unroll
        for (int ks = 0; ks < 2; ks++) {
            unsigned bhf[4][4], bmf[4][4];
#pragma unroll
            for (int np = 0; np < 4; np++) {
                ldmx4(bhf[np], bh  + bOff[np][ks]);
                ldmx4(bmf[np], bmm + bOff[np][ks]);
            }
#pragma unroll
            for (int mt = 0; mt < 2; mt++) {
                unsigned ahf[4], amf[4];
                ldmx4(ahf, ah + aOff[mt][ks]);
                ldmx4(amf, am + aOff[mt][ks]);
#pragma unroll
                for (int nt = 0; nt < 8; nt++) {
                    const unsigned* ph = &bhf[nt >> 1][(nt & 1) * 2];
                    const unsigned* pm = &bmf[nt >> 1][(nt & 1) * 2];
                    mma16816(acc[mt][nt], ahf, ph);
                    mma16816(acc[mt][nt], amf, ph);
                    mma16816(acc[mt][nt], ahf, pm);
                }
            }
        }
        __syncthreads();
    }

    int g = lane >> 2, t = lane & 3;
#pragma unroll
    for (int mt = 0; mt < 2; mt++) {
        int r0 = bm + wr * 32 + mt * 16 + g;
        int r1 = r0 + 8;
#pragma unroll
        for (int nt = 0; nt < 8; nt++) {
            int col = wc * 64 + nt * 8 + t * 2;
            if (r0 < NNODES)
                *(float2*)&g_h1[(long)r0 * F1 + col] = make_float2(acc[mt][nt][0], acc[mt][nt][1]);
            if (r1 < NNODES)
                *(float2*)&g_h1[(long)r1 * F1 + col] = make_float2(acc[mt][nt][2], acc[mt][nt][3]);
        }
    }
}

// ---------------- attention coefficients, layer 1 ----------------
__global__ void k_coeff1(const float* __restrict__ att_s, const float* __restrict__ att_d) {
    int i = blockIdx.x * blockDim.x + threadIdx.x;
    if (i >= NNODES * H1N) return;
    int n = i >> 3, h = i & 7;
    const float* hp = &g_h1[(long)n * F1 + h * C1N];
    float s = 0.f, d = 0.f;
#pragma unroll
    for (int c = 0; c < C1N; c++) {
        float v = hp[c];
        s += v * att_s[h * C1N + c];
        d += v * att_d[h * C1N + c];
    }
    g_as1[i] = s;
    g_ad1[i] = d;
}

// ---------------- layer-1 aggregation: warp/node, pipelined online softmax --
__global__ void k_agg1(const float* __restrict__ b1) {
    int gtid = blockIdx.x * blockDim.x + threadIdx.x;
    int n    = gtid >> 5;
    int lane = threadIdx.x & 31;
    if (n >= NNODES) return;
    int h = lane >> 2;
    int beg = g_rowptr[n], end = g_rowptr[n + 1];
    float adst = g_ad1[n * H1N + h];
    float m = -1e30f, s = 0.f;
    float ax = 0.f, ay = 0.f, az = 0.f, aw = 0.f;

    int   s_p2 = (beg + 1 < end) ? __ldg(&g_csr[beg + 1]) : 0;
    float e_p1 = 0.f;
    float4 v_p1 = make_float4(0.f, 0.f, 0.f, 0.f);
    if (beg < end) {
        int s0 = __ldg(&g_csr[beg]);
        e_p1 = g_as1[s0 * H1N + h];
        v_p1 = *(const float4*)&g_h1[(long)s0 * F1 + lane * 4];
    }
    for (int j = beg; j < end; j++) {
        float  e_c = e_p1 + adst;
        float4 v   = v_p1;
        int s_nxt = s_p2;
        if (j + 2 < end) s_p2 = __ldg(&g_csr[j + 2]);
        if (j + 1 < end) {
            e_p1 = g_as1[s_nxt * H1N + h];
            v_p1 = *(const float4*)&g_h1[(long)s_nxt * F1 + lane * 4];
        }
        float e = (e_c > 0.f) ? e_c : 0.2f * e_c;
        float mnew  = fmaxf(m, e);
        float scale = __expf(m - mnew);
        float w     = __expf(e - mnew);
        s  = s  * scale + w;
        ax = ax * scale + w * v.x;
        ay = ay * scale + w * v.y;
        az = az * scale + w * v.z;
        aw = aw * scale + w * v.w;
        m = mnew;
    }
    float inv = 1.f / (s + 1e-16f);
    float o[4];
    o[0] = ax * inv + b1[lane * 4 + 0];
    o[1] = ay * inv + b1[lane * 4 + 1];
    o[2] = az * inv + b1[lane * 4 + 2];
    o[3] = aw * inv + b1[lane * 4 + 3];
#pragma unroll
    for (int i = 0; i < 4; i++)
        o[i] = (o[i] > 0.f) ? o[i] : (__expf(o[i]) - 1.f);
    *(float4*)&g_h1a[(long)n * F1 + lane * 4] = *(float4*)o;
}

// ---------------- GEMM2: h2 = h1a @ W2 (float4 LDS, padded stride) ---------
#define HP 132
__global__ __launch_bounds__(320) void k_gemm2(const float* __restrict__ W2) {
    __shared__ float hs [32 * HP];
    __shared__ float wst[40 * HP];
    int r0  = blockIdx.x * 32;
    int tid = threadIdx.x;
    for (int i = tid; i < 40 * F1; i += 320) {
        int c = i >> 7, k = i & 127;
        wst[c * HP + k] = W2[k * F2 + c];
    }
    for (int i = tid; i < 32 * F1; i += 320) {
        int r = i >> 7, k = i & 127;
        int gr = r0 + r;
        hs[r * HP + k] = (gr < NNODES) ? g_h1a[(long)gr * F1 + k] : 0.f;
    }
    __syncthreads();
    int c  = tid % 40;
    int rr = tid / 40;
    float acc[4] = {0.f, 0.f, 0.f, 0.f};
    for (int k4 = 0; k4 < F1 / 4; k4++) {
        float4 w = *(float4*)&wst[c * HP + k4 * 4];
#pragma unroll
        for (int i = 0; i < 4; i++) {
            float4 hv = *(float4*)&hs[(rr + i * 8) * HP + k4 * 4];
            acc[i] += w.x * hv.x + w.y * hv.y + w.z * hv.z + w.w * hv.w;
        }
    }
#pragma unroll
    for (int i = 0; i < 4; i++) {
        int gr = r0 + rr + i * 8;
        if (gr < NNODES) g_h2[(long)gr * F2 + c] = acc[i];
    }
}

// ---------------- attention coefficients, layer 2 ----------------
__global__ void k_coeff2(const float* __restrict__ att_s, const float* __restrict__ att_d) {
    int n = blockIdx.x * blockDim.x + threadIdx.x;
    if (n >= NNODES) return;
    const float* hp = &g_h2[(long)n * F2];
    float s = 0.f, d = 0.f;
#pragma unroll
    for (int c = 0; c < F2; c++) {
        float v = hp[c];
        s += v * att_s[c];
        d += v * att_d[c];
    }
    g_as2[n] = s;
    g_ad2[n] = d;
}

// ---------------- layer-2 aggregation + bias + log_softmax ----------------
__global__ void k_agg2(const float* __restrict__ b2, float* __restrict__ out) {
    int gtid = blockIdx.x * blockDim.x + threadIdx.x;
    int n    = gtid >> 5;
    int lane = threadIdx.x & 31;
    if (n >= NNODES) return;
    bool has2 = lane < 8;
    int beg = g_rowptr[n], end = g_rowptr[n + 1];
    float adst = g_ad2[n];
    float m = -1e30f, s = 0.f, a0 = 0.f, a1 = 0.f;

    int   s_p2 = (beg + 1 < end) ? __ldg(&g_csr[beg + 1]) : 0;
    float e_p1 = 0.f, v0_p = 0.f, v1_p = 0.f;
    if (beg < end) {
        int s0 = __ldg(&g_csr[beg]);
        e_p1 = g_as2[s0];
        v0_p = g_h2[(long)s0 * F2 + lane];
        v1_p = has2 ? g_h2[(long)s0 * F2 + 32 + lane] : 0.f;
    }
    for (int j = beg; j < end; j++) {
        float e_c = e_p1 + adst;
        float v0 = v0_p, v1 = v1_p;
        int s_nxt = s_p2;
        if (j + 2 < end) s_p2 = __ldg(&g_csr[j + 2]);
        if (j + 1 < end) {
            e_p1 = g_as2[s_nxt];
            v0_p = g_h2[(long)s_nxt * F2 + lane];
            v1_p = has2 ? g_h2[(long)s_nxt * F2 + 32 + lane] : 0.f;
        }
        float e = (e_c > 0.f) ? e_c : 0.2f * e_c;
        float mnew  = fmaxf(m, e);
        float scale = __expf(m - mnew);
        float w     = __expf(e - mnew);
        s  = s  * scale + w;
        a0 = a0 * scale + w * v0;
        a1 = a1 * scale + w * v1;
        m = mnew;
    }
    float inv = 1.f / (s + 1e-16f);
    float x0 = a0 * inv + b2[lane];
    float x1 = has2 ? (a1 * inv + b2[32 + lane]) : -1e30f;
    float mx = fmaxf(x0, x1);
#pragma unroll
    for (int o = 16; o; o >>= 1) mx = fmaxf(mx, __shfl_xor_sync(0xFFFFFFFFu, mx, o));
    float se = __expf(x0 - mx) + (has2 ? __expf(x1 - mx) : 0.f);
#pragma unroll
    for (int o = 16; o; o >>= 1) se += __shfl_xor_sync(0xFFFFFFFFu, se, o);
    float lse = mx + logf(se);
    out[(long)n * F2 + lane] = x0 - lse;
    if (has2) out[(long)n * F2 + 32 + lane] = x1 - lse;
}

// ---------------- launch ----------------
extern "C" void kernel_launch(void* const* d_in, const int* in_sizes, int n_in,
                              void* d_out, int out_size) {
    const float* x   = (const float*)d_in[0];
    const int*   ei  = (const int*)d_in[1];
    const float* W1  = (const float*)d_in[2];
    const float* as1 = (const float*)d_in[3];
    const float* ad1 = (const float*)d_in[4];
    const float* b1  = (const float*)d_in[5];
    const float* W2  = (const float*)d_in[6];
    const float* as2 = (const float*)d_in[7];
    const float* ad2 = (const float*)d_in[8];
    const float* b2  = (const float*)d_in[9];
    float*       out = (float*)d_out;

    int E    = in_sizes[1] / 2;
    if (E > EMAX) E = EMAX;
    int Etot = E + NNODES;
    int nb   = (NNODES + 1023) / 1024;

    static int smem_set = 0;
    if (!smem_set) {
        cudaFuncSetAttribute(k_gemm1_mma, cudaFuncAttributeMaxDynamicSharedMemorySize, 8 * TILEB);
        smem_set = 1;
    }

    // ordered so launch index 5 (ncu -s 5 -c 1) is k_gemm1_mma
    k_splitB<<<(FIN * F1 + 255) / 256, 256>>>(W1);                 // 0
    k_zero_counts<<<(NNODES + 255) / 256, 256>>>();                // 1
    k_count<<<(Etot + 255) / 256, 256>>>(ei, E, Etot);             // 2
    k_scan1<<<nb, 1024>>>();                                       // 3
    k_scan2<<<1, 32>>>(nb);                                        // 4
    k_gemm1_mma<<<(NNODES + 127) / 128, 256, 8 * TILEB>>>(x);      // 5 <- profiled
    k_scan3<<<(NNODES + 255) / 256, 256>>>(Etot);                  // 6
    k_fill<<<(Etot + 255) / 256, 256>>>(ei, E, Etot);              // 7
    k_coeff1<<<(NNODES * H1N + 255) / 256, 256>>>(as1, ad1);       // 8
    k_agg1<<<(NNODES * 32 + 255) / 256, 256>>>(b1);                // 9
    k_gemm2<<<(NNODES + 31) / 32, 320>>>(W2);                      // 10
    k_coeff2<<<(NNODES + 255) / 256, 256>>>(as2, ad2);             // 11
    k_agg2<<<(NNODES * 32 + 255) / 256, 256>>>(b2, out);           // 12
}

// round 6
// speedup vs baseline: 1.4274x; 1.1288x over previous
#include <cuda_runtime.h>
#include <cuda_bf16.h>

#define NNODES 50000
#define FIN    512
#define H1N    8
#define C1N    16
#define F1     128      // H1*C1
#define F2     40
#define EMAX   800000
#define ETOTMAX (EMAX + NNODES)

// ---------------- static scratch ----------------
__device__ float g_h1 [NNODES * F1];
__device__ float g_h1a[NNODES * F1];
__device__ float g_as1[NNODES * H1N];
__device__ float g_ad1[NNODES * H1N];
__device__ float g_h2 [NNODES * F2];
__device__ float g_as2[NNODES];
__device__ float g_ad2[NNODES];
__device__ int   g_counts[NNODES];
__device__ int   g_rowptr[NNODES + 1];
__device__ int   g_cursor[NNODES];
__device__ int   g_csr[ETOTMAX];
__device__ int   g_bsum[64];

__device__ __nv_bfloat16 g_Bth[F1 * FIN];   // hi(W1) transposed  [n][k]
__device__ __nv_bfloat16 g_Btm[F1 * FIN];   // mid(W1) transposed [n][k]

// ---------------- CSR build ----------------
__global__ void k_zero_counts() {
    int i = blockIdx.x * blockDim.x + threadIdx.x;
    if (i < NNODES) g_counts[i] = 0;
}

__global__ void k_count(const int* __restrict__ ei, int E, int Etot) {
    int i = blockIdx.x * blockDim.x + threadIdx.x;
    if (i >= Etot) return;
    int d = (i < E) ? ei[E + i] : (i - E);
    if (d < 0 || d >= NNODES) return;
    atomicAdd(&g_counts[d], 1);
}

__global__ void k_scan1() {
    __shared__ int tmp[1024];
    int t = threadIdx.x;
    int gid = blockIdx.x * 1024 + t;
    int v = (gid < NNODES) ? g_counts[gid] : 0;
    tmp[t] = v;
    __syncthreads();
    for (int off = 1; off < 1024; off <<= 1) {
        int x = (t >= off) ? tmp[t - off] : 0;
        __syncthreads();
        tmp[t] += x;
        __syncthreads();
    }
    if (gid < NNODES) g_rowptr[gid] = tmp[t] - v;
    if (t == 1023) g_bsum[blockIdx.x] = tmp[1023];
}

__global__ void k_scan2(int nb) {
    if (threadIdx.x == 0) {
        int acc = 0;
        for (int i = 0; i < nb; i++) { int x = g_bsum[i]; g_bsum[i] = acc; acc += x; }
    }
}

__global__ void k_scan3(int Etot) {
    int gid = blockIdx.x * blockDim.x + threadIdx.x;
    if (gid < NNODES) {
        int v = g_rowptr[gid] + g_bsum[gid >> 10];
        g_rowptr[gid] = v;
        g_cursor[gid] = v;
    }
    if (gid == 0) g_rowptr[NNODES] = Etot;
}

__global__ void k_fill(const int* __restrict__ ei, int E, int Etot) {
    int i = blockIdx.x * blockDim.x + threadIdx.x;
    if (i >= Etot) return;
    int s, d;
    if (i < E) { s = ei[i]; d = ei[E + i]; }
    else       { s = d = i - E; }
    if (d < 0 || d >= NNODES || s < 0 || s >= NNODES) return;
    int pos = atomicAdd(&g_cursor[d], 1);
    if (pos < ETOTMAX) g_csr[pos] = s;
}

// ---------------- bf16 split of W1 (tiny: 128KB) ----------------
__global__ void k_splitB(const float* __restrict__ W1) {
    int i = blockIdx.x * blockDim.x + threadIdx.x;
    if (i >= FIN * F1) return;
    int k = i / F1, n = i % F1;
    float v = W1[i];
    __nv_bfloat16 h = __float2bfloat16_rn(v);
    __nv_bfloat16 m = __float2bfloat16_rn(v - __bfloat162float(h));
    g_Bth[n * FIN + k] = h;
    g_Btm[n * FIN + k] = m;
}

// ---------------- GEMM1 + fused coeff1 epilogue ----------------
// h1 = x@W1 via Ah*Bh + Ah*Bm + Am*Bh (in-register fp32->bf16 split), plus
// as1/ad1 computed from accumulators via quad shuffles.
#define SWZ32(row, chk) ((row) * 64 + (((chk) ^ (((row) >> 1) & 3)) << 4))
#define TILEB 8192   // one 128x32 bf16 tile

__device__ __forceinline__ void ldmx4(unsigned* r, unsigned addr) {
    asm volatile("ldmatrix.sync.aligned.m8n8.x4.shared.b16 {%0,%1,%2,%3}, [%4];"
                 : "=r"(r[0]), "=r"(r[1]), "=r"(r[2]), "=r"(r[3]) : "r"(addr));
}

__device__ __forceinline__ void mma16816(float* c, const unsigned* a, const unsigned* b) {
    asm volatile(
        "mma.sync.aligned.m16n8k16.row.col.f32.bf16.bf16.f32 "
        "{%0,%1,%2,%3}, {%4,%5,%6,%7}, {%8,%9}, {%0,%1,%2,%3};"
        : "+f"(c[0]), "+f"(c[1]), "+f"(c[2]), "+f"(c[3])
        : "r"(a[0]), "r"(a[1]), "r"(a[2]), "r"(a[3]), "r"(b[0]), "r"(b[1]));
}

__device__ __forceinline__ void cpasync16(unsigned saddr, const void* gaddr) {
    asm volatile("cp.async.cg.shared.global [%0], [%1], 16;"
                 :: "r"(saddr), "l"(gaddr));
}

extern __shared__ __align__(16) unsigned char dynsmem[];

__global__ __launch_bounds__(256) void k_gemm1_mma(const float* __restrict__ X,
                                                   const float* __restrict__ att_s,
                                                   const float* __restrict__ att_d) {
    const int AH = 0, AM = 2 * TILEB, BH = 4 * TILEB, BMo = 6 * TILEB;
    unsigned base = (unsigned)__cvta_generic_to_shared(dynsmem);

    int tid  = threadIdx.x;
    int lane = tid & 31;
    int wid  = tid >> 5;
    int wr   = wid & 3;
    int wc   = wid >> 2;
    int bm   = blockIdx.x * 128;

    // A fp32 load mapping: 8 threads/row, 4 floats each; 4 rows/thread (+32 apart)
    int arow = tid >> 3;
    int acol = (tid & 7) * 4;
    bool av[4];
    long gA[4];
#pragma unroll
    for (int i = 0; i < 4; i++) {
        int r = bm + arow + 32 * i;
        av[i] = r < NNODES;
        gA[i] = (long)r * FIN;
    }
    unsigned aStOff = SWZ32(arow, acol >> 3) + ((acol & 4) << 1);

    // B cp.async mapping
    int lrow = tid >> 2, lchk = tid & 3;
    unsigned sBo0 = SWZ32(lrow, lchk), sBo1 = SWZ32(lrow + 64, lchk);

    // ldmatrix offsets
    int sub = lane >> 3, r8 = lane & 7;
    unsigned aOff[2][2], bOff[4][2];
#pragma unroll
    for (int mt = 0; mt < 2; mt++) {
        int row = wr * 32 + mt * 16 + (sub & 1) * 8 + r8;
#pragma unroll
        for (int ks = 0; ks < 2; ks++)
            aOff[mt][ks] = SWZ32(row, (sub >> 1) + 2 * ks);
    }
#pragma unroll
    for (int np = 0; np < 4; np++) {
        int row = wc * 64 + np * 16 + (sub >> 1) * 8 + r8;
#pragma unroll
        for (int ks = 0; ks < 2; ks++)
            bOff[np][ks] = SWZ32(row, (sub & 1) + 2 * ks);
    }

    float acc[2][8][4];
#pragma unroll
    for (int mt = 0; mt < 2; mt++)
#pragma unroll
        for (int nt = 0; nt < 8; nt++)
#pragma unroll
            for (int j = 0; j < 4; j++) acc[mt][nt][j] = 0.f;

    const int NIT = FIN / 32;   // 16

    auto issueB = [&](int it, int b) {
        int koff = it * 32;
        cpasync16(base + BH  + b * TILEB + sBo0, &g_Bth[(long)lrow * FIN + koff + lchk * 8]);
        cpasync16(base + BH  + b * TILEB + sBo1, &g_Bth[(long)(lrow + 64) * FIN + koff + lchk * 8]);
        cpasync16(base + BMo + b * TILEB + sBo0, &g_Btm[(long)lrow * FIN + koff + lchk * 8]);
        cpasync16(base + BMo + b * TILEB + sBo1, &g_Btm[(long)(lrow + 64) * FIN + koff + lchk * 8]);
    };
    auto loadA = [&](int it, float4* ra) {
        int koff = it * 32 + acol;
#pragma unroll
        for (int i = 0; i < 4; i++)
            ra[i] = av[i] ? *(const float4*)&X[gA[i] + koff]
                          : make_float4(0.f, 0.f, 0.f, 0.f);
    };

    float4 ra[4];
    issueB(0, 0);
    asm volatile("cp.async.commit_group;" ::);
    loadA(0, ra);

    for (int it = 0; it < NIT; it++) {
        int buf = it & 1;
#pragma unroll
        for (int i = 0; i < 4; i++) {
            float f[4] = {ra[i].x, ra[i].y, ra[i].z, ra[i].w};
            __nv_bfloat16 h[4], m[4];
#pragma unroll
            for (int j = 0; j < 4; j++) {
                h[j] = __float2bfloat16_rn(f[j]);
                m[j] = __float2bfloat16_rn(f[j] - __bfloat162float(h[j]));
            }
            unsigned off = aStOff + 32 * i * 64;
            *(uint2*)(dynsmem + AH + buf * TILEB + off) = *(uint2*)h;
            *(uint2*)(dynsmem + AM + buf * TILEB + off) = *(uint2*)m;
        }
        if (it + 1 < NIT) {
            loadA(it + 1, ra);
            issueB(it + 1, buf ^ 1);
            asm volatile("cp.async.commit_group;" ::);
            asm volatile("cp.async.wait_group 1;" ::);
        } else {
            asm volatile("cp.async.wait_group 0;" ::);
        }
        __syncthreads();

        unsigned ah = base + AH  + buf * TILEB;
        unsigned am = base + AM  + buf * TILEB;
        unsigned bh = base + BH  + buf * TILEB;
        unsigned bmm = base + BMo + buf * TILEB;
#pragma unroll
        for (int ks = 0; ks < 2; ks++) {
            unsigned bhf[4][4], bmf[4][4];
#pragma unroll
            for (int np = 0; np < 4; np++) {
                ldmx4(bhf[np], bh  + bOff[np][ks]);
                ldmx4(bmf[np], bmm + bOff[np][ks]);
            }
#pragma unroll
            for (int mt = 0; mt < 2; mt++) {
                unsigned ahf[4], amf[4];
                ldmx4(ahf, ah + aOff[mt][ks]);
                ldmx4(amf, am + aOff[mt][ks]);
#pragma unroll
                for (int nt = 0; nt < 8; nt++) {
                    const unsigned* ph = &bhf[nt >> 1][(nt & 1) * 2];
                    const unsigned* pm = &bmf[nt >> 1][(nt & 1) * 2];
                    mma16816(acc[mt][nt], ahf, ph);
                    mma16816(acc[mt][nt], amf, ph);
                    mma16816(acc[mt][nt], ahf, pm);
                }
            }
        }
        __syncthreads();
    }

    int g = lane >> 2, t = lane & 3;
    // h1 writeback
#pragma unroll
    for (int mt = 0; mt < 2; mt++) {
        int r0 = bm + wr * 32 + mt * 16 + g;
        int r1 = r0 + 8;
#pragma unroll
        for (int nt = 0; nt < 8; nt++) {
            int col = wc * 64 + nt * 8 + t * 2;
            if (r0 < NNODES)
                *(float2*)&g_h1[(long)r0 * F1 + col] = make_float2(acc[mt][nt][0], acc[mt][nt][1]);
            if (r1 < NNODES)
                *(float2*)&g_h1[(long)r1 * F1 + col] = make_float2(acc[mt][nt][2], acc[mt][nt][3]);
        }
    }
    // fused coeff1: as1/ad1 per (row, head) via quad reduction.
    // head gh = wc*4 + hh covers cols gh*16..gh*16+15 = nt in {2hh, 2hh+1}.
#pragma unroll
    for (int mt = 0; mt < 2; mt++) {
        int r0 = bm + wr * 32 + mt * 16 + g;
        int r1 = r0 + 8;
#pragma unroll
        for (int hh = 0; hh < 4; hh++) {
            float s0 = 0.f, d0 = 0.f, s1 = 0.f, d1 = 0.f;
#pragma unroll
            for (int q = 0; q < 2; q++) {
                int nt  = 2 * hh + q;
                int col = wc * 64 + nt * 8 + t * 2;
                float asv0 = __ldg(&att_s[col]), asv1 = __ldg(&att_s[col + 1]);
                float adv0 = __ldg(&att_d[col]), adv1 = __ldg(&att_d[col + 1]);
                s0 += acc[mt][nt][0] * asv0 + acc[mt][nt][1] * asv1;
                d0 += acc[mt][nt][0] * adv0 + acc[mt][nt][1] * adv1;
                s1 += acc[mt][nt][2] * asv0 + acc[mt][nt][3] * asv1;
                d1 += acc[mt][nt][2] * adv0 + acc[mt][nt][3] * adv1;
            }
#pragma unroll
            for (int o = 1; o <= 2; o <<= 1) {
                s0 += __shfl_xor_sync(0xFFFFFFFFu, s0, o);
                d0 += __shfl_xor_sync(0xFFFFFFFFu, d0, o);
                s1 += __shfl_xor_sync(0xFFFFFFFFu, s1, o);
                d1 += __shfl_xor_sync(0xFFFFFFFFu, d1, o);
            }
            if (t == 0) {
                int gh = wc * 4 + hh;
                if (r0 < NNODES) { g_as1[r0 * H1N + gh] = s0; g_ad1[r0 * H1N + gh] = d0; }
                if (r1 < NNODES) { g_as1[r1 * H1N + gh] = s1; g_ad1[r1 * H1N + gh] = d1; }
            }
        }
    }
}

// ---------------- layer-1 aggregation: warp/node, pipelined online softmax --
__global__ void k_agg1(const float* __restrict__ b1) {
    int gtid = blockIdx.x * blockDim.x + threadIdx.x;
    int n    = gtid >> 5;
    int lane = threadIdx.x & 31;
    if (n >= NNODES) return;
    int h = lane >> 2;
    int beg = g_rowptr[n], end = g_rowptr[n + 1];
    float adst = g_ad1[n * H1N + h];
    float m = -1e30f, s = 0.f;
    float ax = 0.f, ay = 0.f, az = 0.f, aw = 0.f;

    int   s_p2 = (beg + 1 < end) ? __ldg(&g_csr[beg + 1]) : 0;
    float e_p1 = 0.f;
    float4 v_p1 = make_float4(0.f, 0.f, 0.f, 0.f);
    if (beg < end) {
        int s0 = __ldg(&g_csr[beg]);
        e_p1 = g_as1[s0 * H1N + h];
        v_p1 = *(const float4*)&g_h1[(long)s0 * F1 + lane * 4];
    }
    for (int j = beg; j < end; j++) {
        float  e_c = e_p1 + adst;
        float4 v   = v_p1;
        int s_nxt = s_p2;
        if (j + 2 < end) s_p2 = __ldg(&g_csr[j + 2]);
        if (j + 1 < end) {
            e_p1 = g_as1[s_nxt * H1N + h];
            v_p1 = *(const float4*)&g_h1[(long)s_nxt * F1 + lane * 4];
        }
        float e = (e_c > 0.f) ? e_c : 0.2f * e_c;
        float mnew  = fmaxf(m, e);
        float scale = __expf(m - mnew);
        float w     = __expf(e - mnew);
        s  = s  * scale + w;
        ax = ax * scale + w * v.x;
        ay = ay * scale + w * v.y;
        az = az * scale + w * v.z;
        aw = aw * scale + w * v.w;
        m = mnew;
    }
    float inv = 1.f / (s + 1e-16f);
    float o[4];
    o[0] = ax * inv + b1[lane * 4 + 0];
    o[1] = ay * inv + b1[lane * 4 + 1];
    o[2] = az * inv + b1[lane * 4 + 2];
    o[3] = aw * inv + b1[lane * 4 + 3];
#pragma unroll
    for (int i = 0; i < 4; i++)
        o[i] = (o[i] > 0.f) ? o[i] : (__expf(o[i]) - 1.f);
    *(float4*)&g_h1a[(long)n * F1 + lane * 4] = *(float4*)o;
}

// ---------------- GEMM2: h2 = h1a @ W2 ----------------
#define HP 132
__global__ __launch_bounds__(320) void k_gemm2(const float* __restrict__ W2) {
    __shared__ float hs [32 * HP];
    __shared__ float wst[40 * HP];
    int r0  = blockIdx.x * 32;
    int tid = threadIdx.x;
    for (int i = tid; i < 40 * F1; i += 320) {
        int c = i >> 7, k = i & 127;
        wst[c * HP + k] = W2[k * F2 + c];
    }
    for (int i = tid; i < 32 * F1; i += 320) {
        int r = i >> 7, k = i & 127;
        int gr = r0 + r;
        hs[r * HP + k] = (gr < NNODES) ? g_h1a[(long)gr * F1 + k] : 0.f;
    }
    __syncthreads();
    int c  = tid % 40;
    int rr = tid / 40;
    float acc[4] = {0.f, 0.f, 0.f, 0.f};
    for (int k4 = 0; k4 < F1 / 4; k4++) {
        float4 w = *(float4*)&wst[c * HP + k4 * 4];
#pragma unroll
        for (int i = 0; i < 4; i++) {
            float4 hv = *(float4*)&hs[(rr + i * 8) * HP + k4 * 4];
            acc[i] += w.x * hv.x + w.y * hv.y + w.z * hv.z + w.w * hv.w;
        }
    }
#pragma unroll
    for (int i = 0; i < 4; i++) {
        int gr = r0 + rr + i * 8;
        if (gr < NNODES) g_h2[(long)gr * F2 + c] = acc[i];
    }
}

// ---------------- attention coefficients, layer 2 ----------------
__global__ void k_coeff2(const float* __restrict__ att_s, const float* __restrict__ att_d) {
    int n = blockIdx.x * blockDim.x + threadIdx.x;
    if (n >= NNODES) return;
    const float* hp = &g_h2[(long)n * F2];
    float s = 0.f, d = 0.f;
#pragma unroll
    for (int c = 0; c < F2; c++) {
        float v = hp[c];
        s += v * att_s[c];
        d += v * att_d[c];
    }
    g_as2[n] = s;
    g_ad2[n] = d;
}

// ---------------- layer-2 aggregation + bias + log_softmax ----------------
__global__ void k_agg2(const float* __restrict__ b2, float* __restrict__ out) {
    int gtid = blockIdx.x * blockDim.x + threadIdx.x;
    int n    = gtid >> 5;
    int lane = threadIdx.x & 31;
    if (n >= NNODES) return;
    bool has2 = lane < 8;
    int beg = g_rowptr[n], end = g_rowptr[n + 1];
    float adst = g_ad2[n];
    float m = -1e30f, s = 0.f, a0 = 0.f, a1 = 0.f;

    int   s_p2 = (beg + 1 < end) ? __ldg(&g_csr[beg + 1]) : 0;
    float e_p1 = 0.f, v0_p = 0.f, v1_p = 0.f;
    if (beg < end) {
        int s0 = __ldg(&g_csr[beg]);
        e_p1 = g_as2[s0];
        v0_p = g_h2[(long)s0 * F2 + lane];
        v1_p = has2 ? g_h2[(long)s0 * F2 + 32 + lane] : 0.f;
    }
    for (int j = beg; j < end; j++) {
        float e_c = e_p1 + adst;
        float v0 = v0_p, v1 = v1_p;
        int s_nxt = s_p2;
        if (j + 2 < end) s_p2 = __ldg(&g_csr[j + 2]);
        if (j + 1 < end) {
            e_p1 = g_as2[s_nxt];
            v0_p = g_h2[(long)s_nxt * F2 + lane];
            v1_p = has2 ? g_h2[(long)s_nxt * F2 + 32 + lane] : 0.f;
        }
        float e = (e_c > 0.f) ? e_c : 0.2f * e_c;
        float mnew  = fmaxf(m, e);
        float scale = __expf(m - mnew);
        float w     = __expf(e - mnew);
        s  = s  * scale + w;
        a0 = a0 * scale + w * v0;
        a1 = a1 * scale + w * v1;
        m = mnew;
    }
    float inv = 1.f / (s + 1e-16f);
    float x0 = a0 * inv + b2[lane];
    float x1 = has2 ? (a1 * inv + b2[32 + lane]) : -1e30f;
    float mx = fmaxf(x0, x1);
#pragma unroll
    for (int o = 16; o; o >>= 1) mx = fmaxf(mx, __shfl_xor_sync(0xFFFFFFFFu, mx, o));
    float se = __expf(x0 - mx) + (has2 ? __expf(x1 - mx) : 0.f);
#pragma unroll
    for (int o = 16; o; o >>= 1) se += __shfl_xor_sync(0xFFFFFFFFu, se, o);
    float lse = mx + logf(se);
    out[(long)n * F2 + lane] = x0 - lse;
    if (has2) out[(long)n * F2 + 32 + lane] = x1 - lse;
}

// ---------------- launch ----------------
extern "C" void kernel_launch(void* const* d_in, const int* in_sizes, int n_in,
                              void* d_out, int out_size) {
    const float* x   = (const float*)d_in[0];
    const int*   ei  = (const int*)d_in[1];
    const float* W1  = (const float*)d_in[2];
    const float* as1 = (const float*)d_in[3];
    const float* ad1 = (const float*)d_in[4];
    const float* b1  = (const float*)d_in[5];
    const float* W2  = (const float*)d_in[6];
    const float* as2 = (const float*)d_in[7];
    const float* ad2 = (const float*)d_in[8];
    const float* b2  = (const float*)d_in[9];
    float*       out = (float*)d_out;

    int E    = in_sizes[1] / 2;
    if (E > EMAX) E = EMAX;
    int Etot = E + NNODES;
    int nb   = (NNODES + 1023) / 1024;

    static cudaStream_t sA = nullptr, sB = nullptr;
    static cudaEvent_t  e0, eA, eB;
    if (!sA) {
        cudaStreamCreateWithFlags(&sA, cudaStreamNonBlocking);
        cudaStreamCreateWithFlags(&sB, cudaStreamNonBlocking);
        cudaEventCreateWithFlags(&e0, cudaEventDisableTiming);
        cudaEventCreateWithFlags(&eA, cudaEventDisableTiming);
        cudaEventCreateWithFlags(&eB, cudaEventDisableTiming);
        cudaFuncSetAttribute(k_gemm1_mma, cudaFuncAttributeMaxDynamicSharedMemorySize, 8 * TILEB);
    }

    // fork both worker streams off the capture-origin (legacy default) stream
    cudaEventRecord(e0, 0);
    cudaStreamWaitEvent(sA, e0, 0);
    cudaStreamWaitEvent(sB, e0, 0);

    // enqueue order chosen so launch index 3 = k_gemm1_mma (ncu window)
    k_zero_counts<<<(NNODES + 255) / 256, 256, 0, sB>>>();                    // 0
    k_count<<<(Etot + 255) / 256, 256, 0, sB>>>(ei, E, Etot);                 // 1
    k_splitB<<<(FIN * F1 + 255) / 256, 256, 0, sA>>>(W1);                     // 2
    k_gemm1_mma<<<(NNODES + 127) / 128, 256, 8 * TILEB, sA>>>(x, as1, ad1);   // 3 <- profiled
    k_scan1<<<nb, 1024, 0, sB>>>();                                           // 4
    k_scan2<<<1, 32, 0, sB>>>(nb);                                            // 5
    k_scan3<<<(NNODES + 255) / 256, 256, 0, sB>>>(Etot);                      // 6
    k_fill<<<(Etot + 255) / 256, 256, 0, sB>>>(ei, E, Etot);                  // 7

    // join back on the default stream
    cudaEventRecord(eA, sA);
    cudaEventRecord(eB, sB);
    cudaStreamWaitEvent(0, eA, 0);
    cudaStreamWaitEvent(0, eB, 0);

    k_agg1<<<(NNODES * 32 + 255) / 256, 256>>>(b1);                           // 8
    k_gemm2<<<(NNODES + 31) / 32, 320>>>(W2);                                 // 9
    k_coeff2<<<(NNODES + 255) / 256, 256>>>(as2, ad2);                        // 10
    k_agg2<<<(NNODES * 32 + 255) / 256, 256>>>(b2, out);                      // 11
}